// round 4
// baseline (speedup 1.0000x reference)
#include <cuda_runtime.h>
#include <cstdint>
#include <math.h>

#define EPSF 1e-5f

constexpr int B_  = 2, T_ = 16, S_ = 256, C_ = 1024, H_ = 16;
constexpr int R_  = B_ * T_ * S_;   // 8192 tokens
constexpr int HID_ = 4 * C_;        // 4096
constexpr float SCALE_ = 8.0f / 64.0f;

// ---- scratch (device globals; no runtime allocation allowed) ----
__device__ float g_xbuf[R_ * C_];
__device__ float g_xln [R_ * C_];
__device__ float g_qkv [R_ * 3 * C_];
__device__ float g_attn[R_ * C_];
__device__ float g_xt  [R_ * C_];
__device__ float g_h   [R_ * HID_];
// transposed (tf32-rounded) weights, [N,K] row-major
__device__ float g_wt_sqkv [3 * C_ * C_];
__device__ float g_wt_sproj[C_ * C_];
__device__ float g_wt_tqkv [3 * C_ * C_];
__device__ float g_wt_tproj[C_ * C_];
__device__ float g_wt_fc1  [HID_ * C_];
__device__ float g_wt_fc2  [C_ * HID_];

__device__ __forceinline__ uint32_t smem_u32(const void* p) {
    uint32_t a;
    asm("{ .reg .u64 t; cvta.to.shared.u64 t, %1; cvt.u32.u64 %0, t; }" : "=r"(a) : "l"(p));
    return a;
}
__device__ __forceinline__ float to_tf32(float x) {
    float r;
    asm("cvt.rna.tf32.f32 %0, %1;" : "=f"(r) : "f"(x));
    return r;
}
__device__ __forceinline__ float lds_f(uint32_t a) {
    float v;
    asm volatile("ld.shared.f32 %0, [%1];" : "=f"(v) : "r"(a));
    return v;
}
__device__ __forceinline__ void mma_tf32(float c[4], const uint32_t a[4], const uint32_t b[2]) {
    asm volatile("mma.sync.aligned.m16n8k8.row.col.f32.tf32.tf32.f32 "
        "{%0,%1,%2,%3}, {%4,%5,%6,%7}, {%8,%9}, {%0,%1,%2,%3};"
        : "+f"(c[0]), "+f"(c[1]), "+f"(c[2]), "+f"(c[3])
        : "r"(a[0]), "r"(a[1]), "r"(a[2]), "r"(a[3]), "r"(b[0]), "r"(b[1]));
}

// ============================================================
// Weight transpose + tf32 round: in [K,N] -> out [N,K]
// ============================================================
__global__ void transpose_w(const float* __restrict__ in, float* __restrict__ out,
                            int K, int N)
{
    __shared__ float t[32][33];
    const int n0 = blockIdx.x * 32, k0 = blockIdx.y * 32;
    const int x = threadIdx.x, y = threadIdx.y;
    #pragma unroll
    for (int i = 0; i < 32; i += 8)
        t[y + i][x] = in[(size_t)(k0 + y + i) * N + n0 + x];
    __syncthreads();
    #pragma unroll
    for (int i = 0; i < 32; i += 8)
        out[(size_t)(n0 + y + i) * K + k0 + x] = to_tf32(t[x][y + i]);
}

// ============================================================
// LayerNorm over C=1024 (tf32-rounded output: feeds GEMM A)
// ============================================================
__global__ void ln_kernel(const float* __restrict__ in, float* __restrict__ out,
                          const float* __restrict__ w, const float* __restrict__ b)
{
    const int row = blockIdx.x, tid = threadIdx.x;
    const float4 xv = reinterpret_cast<const float4*>(in + (size_t)row * 1024)[tid];
    float s  = xv.x + xv.y + xv.z + xv.w;
    float ss = xv.x*xv.x + xv.y*xv.y + xv.z*xv.z + xv.w*xv.w;
    __shared__ float sb[32], ssb[32];
    const int lane = tid & 31, wid = tid >> 5;
    #pragma unroll
    for (int o = 16; o; o >>= 1) {
        s  += __shfl_xor_sync(0xffffffffu, s,  o);
        ss += __shfl_xor_sync(0xffffffffu, ss, o);
    }
    if (lane == 0) { sb[wid] = s; ssb[wid] = ss; }
    __syncthreads();
    if (tid == 0) {
        float ts = 0.f, tss = 0.f;
        #pragma unroll
        for (int i = 0; i < 8; i++) { ts += sb[i]; tss += ssb[i]; }
        float mean = ts * (1.f / 1024.f);
        sb[0]  = mean;
        ssb[0] = rsqrtf(tss * (1.f / 1024.f) - mean * mean + EPSF);
    }
    __syncthreads();
    const float mean = sb[0], rstd = ssb[0];
    const float4 wv = reinterpret_cast<const float4*>(w)[tid];
    const float4 bv = reinterpret_cast<const float4*>(b)[tid];
    float4 o;
    o.x = to_tf32((xv.x - mean) * rstd * wv.x + bv.x);
    o.y = to_tf32((xv.y - mean) * rstd * wv.y + bv.y);
    o.z = to_tf32((xv.z - mean) * rstd * wv.z + bv.z);
    o.w = to_tf32((xv.w - mean) * rstd * wv.w + bv.w);
    reinterpret_cast<float4*>(out + (size_t)row * 1024)[tid] = o;
}

// ============================================================
// Per-head LN (hd=64) on q and k slices of the qkv buffer.
// ============================================================
__global__ void headln_kernel(float* __restrict__ qkv, const float* __restrict__ w,
                              const float* __restrict__ b, float qscale)
{
    const int gw   = (blockIdx.x * blockDim.x + threadIdx.x) >> 5;
    const int lane = threadIdx.x & 31;
    const int r     = gw >> 5;
    const int rem   = gw & 31;
    const int which = rem >> 4;
    const int h     = rem & 15;
    float* p = qkv + (size_t)r * 3072 + which * 1024 + h * 64;
    const float v0 = p[lane], v1 = p[lane + 32];
    float s = v0 + v1, ss = v0*v0 + v1*v1;
    #pragma unroll
    for (int o = 16; o; o >>= 1) {
        s  += __shfl_xor_sync(0xffffffffu, s,  o);
        ss += __shfl_xor_sync(0xffffffffu, ss, o);
    }
    const float mean = s * (1.f / 64.f);
    const float rstd = rsqrtf(ss * (1.f / 64.f) - mean * mean + EPSF);
    const float sc = which ? 1.f : qscale;
    p[lane]      = ((v0 - mean) * rstd * w[lane]      + b[lane])      * sc;
    p[lane + 32] = ((v1 - mean) * rstd * w[lane + 32] + b[lane + 32]) * sc;
}

// ============================================================
// Spatial attention (N=256): one block per (batch, head)
// ============================================================
__global__ void attn_kernel(const float* __restrict__ qkv, float* __restrict__ out)
{
    constexpr int N = 256;
    extern __shared__ float sm[];
    float* Ks = sm;
    float* Vs = sm + N * 64;
    const int bh = blockIdx.x;
    const int h = bh & 15;
    const int batch = bh >> 4;
    const float* base = qkv + (size_t)batch * N * 3072;
    const int tid = threadIdx.x;

    for (int idx = tid; idx < N * 16; idx += N) {
        const int j = idx >> 4, d4 = idx & 15;
        const float4* kp = reinterpret_cast<const float4*>(base + (size_t)j * 3072 + 1024 + h * 64);
        const float4* vp = reinterpret_cast<const float4*>(base + (size_t)j * 3072 + 2048 + h * 64);
        reinterpret_cast<float4*>(Ks + j * 64)[d4] = kp[d4];
        reinterpret_cast<float4*>(Vs + j * 64)[d4] = vp[d4];
    }
    __syncthreads();

    float4 q[16];
    const float4* qp = reinterpret_cast<const float4*>(base + (size_t)tid * 3072 + h * 64);
    #pragma unroll
    for (int d = 0; d < 16; d++) q[d] = qp[d];

    float m = -1e30f;
    for (int j = 0; j < N; j++) {
        const float4* kr = reinterpret_cast<const float4*>(Ks + j * 64);
        float s = 0.f;
        #pragma unroll
        for (int d = 0; d < 16; d++) {
            const float4 kv = kr[d];
            s += q[d].x*kv.x + q[d].y*kv.y + q[d].z*kv.z + q[d].w*kv.w;
        }
        m = fmaxf(m, s);
    }

    float4 acc[16];
    #pragma unroll
    for (int d = 0; d < 16; d++) acc[d] = make_float4(0.f, 0.f, 0.f, 0.f);
    float sum = 0.f;
    for (int j = 0; j < N; j++) {
        const float4* kr = reinterpret_cast<const float4*>(Ks + j * 64);
        float s = 0.f;
        #pragma unroll
        for (int d = 0; d < 16; d++) {
            const float4 kv = kr[d];
            s += q[d].x*kv.x + q[d].y*kv.y + q[d].z*kv.z + q[d].w*kv.w;
        }
        const float e = __expf(s - m);
        sum += e;
        const float4* vr = reinterpret_cast<const float4*>(Vs + j * 64);
        #pragma unroll
        for (int d = 0; d < 16; d++) {
            const float4 vv = vr[d];
            acc[d].x += e * vv.x; acc[d].y += e * vv.y;
            acc[d].z += e * vv.z; acc[d].w += e * vv.w;
        }
    }
    const float inv = 1.f / sum;
    float4* op = reinterpret_cast<float4*>(out + ((size_t)batch * N + tid) * 1024 + h * 64);
    #pragma unroll
    for (int d = 0; d < 16; d++)
        op[d] = make_float4(to_tf32(acc[d].x * inv), to_tf32(acc[d].y * inv),
                            to_tf32(acc[d].z * inv), to_tf32(acc[d].w * inv));
}

// ============================================================
// Temporal attention (N=16): 256-thread blocks, 16 (batch,head)
// groups per block (group = tid>>4, query row = tid&15).
// K/V read straight from global (L1-resident, shared in-group).
// ============================================================
__global__ void attn16_kernel(const float* __restrict__ qkv, float* __restrict__ out)
{
    constexpr int N = 16;
    const int tid = threadIdx.x;
    const int bh = blockIdx.x * 16 + (tid >> 4);
    const int h = bh & 15;
    const int batch = bh >> 4;
    const int row = tid & 15;
    const float* base = qkv + (size_t)batch * N * 3072;

    float4 q[16];
    const float4* qp = reinterpret_cast<const float4*>(base + (size_t)row * 3072 + h * 64);
    #pragma unroll
    for (int d = 0; d < 16; d++) q[d] = qp[d];

    float sc[N];
    float m = -1e30f;
    #pragma unroll
    for (int j = 0; j < N; j++) {
        const float4* kr = reinterpret_cast<const float4*>(base + (size_t)j * 3072 + 1024 + h * 64);
        float s = 0.f;
        #pragma unroll
        for (int d = 0; d < 16; d++) {
            const float4 kv = kr[d];
            s += q[d].x*kv.x + q[d].y*kv.y + q[d].z*kv.z + q[d].w*kv.w;
        }
        sc[j] = s;
        m = fmaxf(m, s);
    }
    float sum = 0.f;
    #pragma unroll
    for (int j = 0; j < N; j++) { sc[j] = __expf(sc[j] - m); sum += sc[j]; }
    const float inv = 1.f / sum;

    float4 acc[16];
    #pragma unroll
    for (int d = 0; d < 16; d++) acc[d] = make_float4(0.f, 0.f, 0.f, 0.f);
    #pragma unroll
    for (int j = 0; j < N; j++) {
        const float e = sc[j];
        const float4* vr = reinterpret_cast<const float4*>(base + (size_t)j * 3072 + 2048 + h * 64);
        #pragma unroll
        for (int d = 0; d < 16; d++) {
            const float4 vv = vr[d];
            acc[d].x += e * vv.x; acc[d].y += e * vv.y;
            acc[d].z += e * vv.z; acc[d].w += e * vv.w;
        }
    }
    float4* op = reinterpret_cast<float4*>(out + ((size_t)batch * N + row) * 1024 + h * 64);
    #pragma unroll
    for (int d = 0; d < 16; d++)
        op[d] = make_float4(to_tf32(acc[d].x * inv), to_tf32(acc[d].y * inv),
                            to_tf32(acc[d].z * inv), to_tf32(acc[d].w * inv));
}

// ============================================================
// (B,T,S,C) <-> (B,S,T,C) row permutation
// ============================================================
__global__ void permute_kernel(const float* __restrict__ src, float* __restrict__ dst, int fwd)
{
    const int rt = blockIdx.x;
    int in_row;
    if (fwd) {
        const int t = rt & 15;  const int bs = rt >> 4;
        const int s = bs & 255; const int b  = bs >> 8;
        in_row = (b * 16 + t) * 256 + s;
    } else {
        const int s = rt & 255; const int bt = rt >> 8;
        const int t = bt & 15;  const int b  = bt >> 4;
        in_row = (b * 256 + s) * 16 + t;
    }
    const float4* sp = reinterpret_cast<const float4*>(src + (size_t)in_row * 1024);
    float4* dp = reinterpret_cast<float4*>(dst + (size_t)rt * 1024);
    dp[threadIdx.x] = sp[threadIdx.x];
}

// ============================================================
// Tensor-core GEMM via mma.sync (tf32):
//   C[M,N] = A[M,K] @ Bt[N,K]^T  (+bias)(+resid)(+gelu)(+round)
// 128x128 tile per CTA, BK=32, THREE-stage cp.async pipeline.
// XOR-swizzled packed smem (128 rows x 128B, chunk c' = c ^ (r&7))
// -> conflict-free fragment LDS, 16KB per tile, 96KB per CTA.
// 8 warps in 4(M) x 2(N): warp tile 32x64 = 2x8 m16n8k8 tiles.
// ============================================================
constexpr int STG_B   = 32768;            // bytes per stage (A 16KB + B 16KB)
constexpr int GEMM_SMEM = 3 * STG_B;      // 98304 B

template<bool GELU, bool ROUND>
__global__ __launch_bounds__(256, 2) void gemm_mma(
    const float* __restrict__ A, const float* __restrict__ Bt,
    float* __restrict__ Cm, const float* __restrict__ bias,
    const float* __restrict__ resid, int M, int N, int K)
{
    extern __shared__ float sm[];
    const uint32_t stg = smem_u32(sm);

    const int tid = threadIdx.x;
    const int wid = tid >> 5, lane = tid & 31;
    const int g = lane >> 2, tig = lane & 3;     // mma fragment coords
    const int warpM = wid & 3, warpN = wid >> 2; // 4x2 warp grid
    const int bx = blockIdx.x, by = blockIdx.y;
    const int NKB = K >> 5;

    // cp.async assignments: 4 chunks of 16B for A, 4 for B (swizzled dst)
    uint32_t a_s[4], b_s[4];
    const float *a_g[4], *b_g[4];
    #pragma unroll
    for (int t = 0; t < 4; t++) {
        const int idx = tid + (t << 8);          // 0..1023
        const int r = idx >> 3, c = idx & 7;     // row, 16B k-chunk
        const uint32_t sw = (uint32_t)(r * 128 + ((c ^ (r & 7)) << 4));
        a_s[t] = sw;            b_s[t] = sw + 16384;
        a_g[t] = A  + (size_t)(by * 128 + r) * K + c * 4;
        b_g[t] = Bt + (size_t)(bx * 128 + r) * K + c * 4;
    }

    auto load_stage = [&](int s, int kb) {
        const uint32_t sb = stg + s * STG_B;
        const int ko = kb << 5;
        #pragma unroll
        for (int t = 0; t < 4; t++)
            asm volatile("cp.async.cg.shared.global [%0], [%1], 16;" ::
                "r"(sb + a_s[t]), "l"(a_g[t] + ko) : "memory");
        #pragma unroll
        for (int t = 0; t < 4; t++)
            asm volatile("cp.async.cg.shared.global [%0], [%1], 16;" ::
                "r"(sb + b_s[t]), "l"(b_g[t] + ko) : "memory");
    };

    float acc[2][8][4];
    #pragma unroll
    for (int mt = 0; mt < 2; mt++)
        #pragma unroll
        for (int nt = 0; nt < 8; nt++)
            #pragma unroll
            for (int i = 0; i < 4; i++) acc[mt][nt][i] = 0.f;

    load_stage(0, 0);
    asm volatile("cp.async.commit_group;" ::: "memory");
    load_stage(1, 1);
    asm volatile("cp.async.commit_group;" ::: "memory");

    // per-thread fragment byte offsets within a tile
    const uint32_t aRow0 = (uint32_t)((warpM * 32 + g) * 128 + tig * 4);
    const uint32_t bRow0 = (uint32_t)((warpN * 64 + g) * 128 + tig * 4);

    for (int kb = 0; kb < NKB; kb++) {
        const int s = kb % 3;
        if (kb + 2 < NKB) load_stage((kb + 2) % 3, kb + 2);
        asm volatile("cp.async.commit_group;" ::: "memory");
        asm volatile("cp.async.wait_group 2;" ::: "memory");
        __syncthreads();

        const uint32_t sA = stg + s * STG_B;
        const uint32_t sB = sA + 16384;
        #pragma unroll
        for (int ks = 0; ks < 4; ks++) {
            const uint32_t x0 = (uint32_t)(((2 * ks)     ^ g) << 4);
            const uint32_t x1 = (uint32_t)(((2 * ks + 1) ^ g) << 4);
            uint32_t a[2][4], b[8][2];
            #pragma unroll
            for (int mt = 0; mt < 2; mt++) {
                const uint32_t rb = sA + aRow0 + (uint32_t)(mt * 16 * 128);
                a[mt][0] = __float_as_uint(lds_f(rb + x0));
                a[mt][1] = __float_as_uint(lds_f(rb + 8 * 128 + x0));
                a[mt][2] = __float_as_uint(lds_f(rb + x1));
                a[mt][3] = __float_as_uint(lds_f(rb + 8 * 128 + x1));
            }
            #pragma unroll
            for (int nt = 0; nt < 8; nt++) {
                const uint32_t rb = sB + bRow0 + (uint32_t)(nt * 8 * 128);
                b[nt][0] = __float_as_uint(lds_f(rb + x0));
                b[nt][1] = __float_as_uint(lds_f(rb + x1));
            }
            #pragma unroll
            for (int mt = 0; mt < 2; mt++)
                #pragma unroll
                for (int nt = 0; nt < 8; nt++)
                    mma_tf32(acc[mt][nt], a[mt], b[nt]);
        }
        __syncthreads();
    }

    // ---- epilogue ----
    #pragma unroll
    for (int mt = 0; mt < 2; mt++) {
        #pragma unroll
        for (int half = 0; half < 2; half++) {
            const int row = by * 128 + warpM * 32 + mt * 16 + g + half * 8;
            float* cp = Cm + (size_t)row * N;
            const float* rp = resid ? resid + (size_t)row * N : nullptr;
            #pragma unroll
            for (int nt = 0; nt < 8; nt++) {
                const int col = bx * 128 + warpN * 64 + nt * 8 + tig * 2;
                float v0 = acc[mt][nt][half * 2 + 0];
                float v1 = acc[mt][nt][half * 2 + 1];
                if (bias) { v0 += bias[col]; v1 += bias[col + 1]; }
                if (rp)   { v0 += rp[col];   v1 += rp[col + 1]; }
                if (GELU) {
                    v0 = 0.5f * v0 * (1.f + erff(v0 * 0.70710678f));
                    v1 = 0.5f * v1 * (1.f + erff(v1 * 0.70710678f));
                }
                if (ROUND) { v0 = to_tf32(v0); v1 = to_tf32(v1); }
                float2 v; v.x = v0; v.y = v1;
                *reinterpret_cast<float2*>(cp + col) = v;
            }
        }
    }
}

// ============================================================
extern "C" void kernel_launch(void* const* d_in, const int* /*in_sizes*/, int /*n_in*/,
                              void* d_out, int /*out_size*/)
{
    const float* x        = (const float*)d_in[0];
    const float* ns_w     = (const float*)d_in[1];
    const float* ns_b     = (const float*)d_in[2];
    const float* nt_w     = (const float*)d_in[3];
    const float* nt_b     = (const float*)d_in[4];
    const float* nm_w     = (const float*)d_in[5];
    const float* nm_b     = (const float*)d_in[6];
    const float* s_qkv    = (const float*)d_in[7];
    const float* s_qkn_w  = (const float*)d_in[8];
    const float* s_qkn_b  = (const float*)d_in[9];
    const float* s_proj_w = (const float*)d_in[10];
    const float* s_proj_b = (const float*)d_in[11];
    const float* t_qkv    = (const float*)d_in[12];
    const float* t_qkn_w  = (const float*)d_in[13];
    const float* t_qkn_b  = (const float*)d_in[14];
    const float* t_proj_w = (const float*)d_in[15];
    const float* t_proj_b = (const float*)d_in[16];
    const float* fc1_w    = (const float*)d_in[17];
    const float* fc1_b    = (const float*)d_in[18];
    const float* fc2_w    = (const float*)d_in[19];
    const float* fc2_b    = (const float*)d_in[20];
    float* out = (float*)d_out;

    float *xbuf, *xln, *qkv, *attn, *xt, *hbuf;
    float *wt_sqkv, *wt_sproj, *wt_tqkv, *wt_tproj, *wt_fc1, *wt_fc2;
    cudaGetSymbolAddress((void**)&xbuf, g_xbuf);
    cudaGetSymbolAddress((void**)&xln,  g_xln);
    cudaGetSymbolAddress((void**)&qkv,  g_qkv);
    cudaGetSymbolAddress((void**)&attn, g_attn);
    cudaGetSymbolAddress((void**)&xt,   g_xt);
    cudaGetSymbolAddress((void**)&hbuf, g_h);
    cudaGetSymbolAddress((void**)&wt_sqkv,  g_wt_sqkv);
    cudaGetSymbolAddress((void**)&wt_sproj, g_wt_sproj);
    cudaGetSymbolAddress((void**)&wt_tqkv,  g_wt_tqkv);
    cudaGetSymbolAddress((void**)&wt_tproj, g_wt_tproj);
    cudaGetSymbolAddress((void**)&wt_fc1,   g_wt_fc1);
    cudaGetSymbolAddress((void**)&wt_fc2,   g_wt_fc2);

    cudaFuncSetAttribute(attn_kernel, cudaFuncAttributeMaxDynamicSharedMemorySize,
                         256 * 64 * 2 * (int)sizeof(float));
    cudaFuncSetAttribute(gemm_mma<false, false>, cudaFuncAttributeMaxDynamicSharedMemorySize, GEMM_SMEM);
    cudaFuncSetAttribute(gemm_mma<true,  true >, cudaFuncAttributeMaxDynamicSharedMemorySize, GEMM_SMEM);

    // ---- weight transposes (+ tf32 rounding), once per launch ----
    dim3 tb(32, 8);
    transpose_w<<<dim3(3072/32, 1024/32), tb>>>(s_qkv,    wt_sqkv,  1024, 3072);
    transpose_w<<<dim3(1024/32, 1024/32), tb>>>(s_proj_w, wt_sproj, 1024, 1024);
    transpose_w<<<dim3(3072/32, 1024/32), tb>>>(t_qkv,    wt_tqkv,  1024, 3072);
    transpose_w<<<dim3(1024/32, 1024/32), tb>>>(t_proj_w, wt_tproj, 1024, 1024);
    transpose_w<<<dim3(4096/32, 1024/32), tb>>>(fc1_w,    wt_fc1,   1024, 4096);
    transpose_w<<<dim3(1024/32, 4096/32), tb>>>(fc2_w,    wt_fc2,   4096, 1024);

    const int hl_blocks = (R_ * 2 * H_) / 8;

    // ---- spatial attention block ----
    ln_kernel<<<R_, 256>>>(x, xln, ns_w, ns_b);
    gemm_mma<false, false><<<dim3(24, 64), 256, GEMM_SMEM>>>(xln, wt_sqkv, qkv, nullptr, nullptr, R_, 3072, 1024);
    headln_kernel<<<hl_blocks, 256>>>(qkv, s_qkn_w, s_qkn_b, SCALE_);
    attn_kernel<<<B_ * T_ * H_, 256, 256 * 64 * 2 * sizeof(float)>>>(qkv, attn);
    gemm_mma<false, false><<<dim3(8, 64), 256, GEMM_SMEM>>>(attn, wt_sproj, xbuf, s_proj_b, x, R_, 1024, 1024);

    // ---- temporal attention block ----
    permute_kernel<<<R_, 256>>>(xbuf, xt, 1);
    ln_kernel<<<R_, 256>>>(xt, xln, nt_w, nt_b);
    gemm_mma<false, false><<<dim3(24, 64), 256, GEMM_SMEM>>>(xln, wt_tqkv, qkv, nullptr, nullptr, R_, 3072, 1024);
    headln_kernel<<<hl_blocks, 256>>>(qkv, t_qkn_w, t_qkn_b, SCALE_);
    attn16_kernel<<<(B_ * S_ * H_) / 16, 256>>>(qkv, attn);
    gemm_mma<false, false><<<dim3(8, 64), 256, GEMM_SMEM>>>(attn, wt_tproj, xln, t_proj_b, xt, R_, 1024, 1024);
    permute_kernel<<<R_, 256>>>(xln, xbuf, 0);

    // ---- MLP ----
    ln_kernel<<<R_, 256>>>(xbuf, xln, nm_w, nm_b);
    gemm_mma<true,  true ><<<dim3(32, 64), 256, GEMM_SMEM>>>(xln, wt_fc1, hbuf, fc1_b, nullptr, R_, 4096, 1024);
    gemm_mma<false, false><<<dim3(8, 64), 256, GEMM_SMEM>>>(hbuf, wt_fc2, out, fc2_b, xbuf, R_, 1024, 4096);
}

// round 5
// speedup vs baseline: 1.8458x; 1.8458x over previous
#include <cuda_runtime.h>
#include <cstdint>
#include <math.h>

#define EPSF 1e-5f

constexpr int B_  = 2, T_ = 16, S_ = 256, C_ = 1024, H_ = 16;
constexpr int R_  = B_ * T_ * S_;   // 8192 tokens
constexpr int HID_ = 4 * C_;        // 4096
constexpr float SCALE_ = 8.0f / 64.0f;
constexpr float ESHIFT = 8.0f;      // softmax overflow guard (replaces max pass)

// ---- scratch (device globals; no runtime allocation allowed) ----
__device__ float g_xbuf[R_ * C_];
__device__ float g_xln [R_ * C_];
__device__ float g_qkv [R_ * 3 * C_];
__device__ float g_attn[R_ * C_];
__device__ float g_xt  [R_ * C_];
__device__ float g_h   [R_ * HID_];
// transposed (tf32-rounded) weights, [N,K] row-major
__device__ float g_wt_sqkv [3 * C_ * C_];
__device__ float g_wt_sproj[C_ * C_];
__device__ float g_wt_tqkv [3 * C_ * C_];
__device__ float g_wt_tproj[C_ * C_];
__device__ float g_wt_fc1  [HID_ * C_];
__device__ float g_wt_fc2  [C_ * HID_];

__device__ __forceinline__ uint32_t smem_u32(const void* p) {
    uint32_t a;
    asm("{ .reg .u64 t; cvta.to.shared.u64 t, %1; cvt.u32.u64 %0, t; }" : "=r"(a) : "l"(p));
    return a;
}
__device__ __forceinline__ float to_tf32(float x) {
    float r;
    asm("cvt.rna.tf32.f32 %0, %1;" : "=f"(r) : "f"(x));
    return r;
}
__device__ __forceinline__ void ldsm4(uint32_t& r0, uint32_t& r1, uint32_t& r2,
                                      uint32_t& r3, uint32_t addr) {
    asm volatile("ldmatrix.sync.aligned.m8n8.x4.b16 {%0,%1,%2,%3}, [%4];"
        : "=r"(r0), "=r"(r1), "=r"(r2), "=r"(r3) : "r"(addr));
}
__device__ __forceinline__ void mma_tf32(float c[4], const uint32_t a[4], const uint32_t b[2]) {
    asm volatile("mma.sync.aligned.m16n8k8.row.col.f32.tf32.tf32.f32 "
        "{%0,%1,%2,%3}, {%4,%5,%6,%7}, {%8,%9}, {%0,%1,%2,%3};"
        : "+f"(c[0]), "+f"(c[1]), "+f"(c[2]), "+f"(c[3])
        : "r"(a[0]), "r"(a[1]), "r"(a[2]), "r"(a[3]), "r"(b[0]), "r"(b[1]));
}

// ============================================================
// Weight transpose + tf32 round: in [K,N] -> out [N,K]
// ============================================================
__global__ void transpose_w(const float* __restrict__ in, float* __restrict__ out,
                            int K, int N)
{
    __shared__ float t[32][33];
    const int n0 = blockIdx.x * 32, k0 = blockIdx.y * 32;
    const int x = threadIdx.x, y = threadIdx.y;
    #pragma unroll
    for (int i = 0; i < 32; i += 8)
        t[y + i][x] = in[(size_t)(k0 + y + i) * N + n0 + x];
    __syncthreads();
    #pragma unroll
    for (int i = 0; i < 32; i += 8)
        out[(size_t)(n0 + y + i) * K + k0 + x] = to_tf32(t[x][y + i]);
}

// ============================================================
// LayerNorm over C=1024 (tf32-rounded output: feeds GEMM A)
// ============================================================
__global__ void ln_kernel(const float* __restrict__ in, float* __restrict__ out,
                          const float* __restrict__ w, const float* __restrict__ b)
{
    const int row = blockIdx.x, tid = threadIdx.x;
    const float4 xv = reinterpret_cast<const float4*>(in + (size_t)row * 1024)[tid];
    float s  = xv.x + xv.y + xv.z + xv.w;
    float ss = xv.x*xv.x + xv.y*xv.y + xv.z*xv.z + xv.w*xv.w;
    __shared__ float sb[32], ssb[32];
    const int lane = tid & 31, wid = tid >> 5;
    #pragma unroll
    for (int o = 16; o; o >>= 1) {
        s  += __shfl_xor_sync(0xffffffffu, s,  o);
        ss += __shfl_xor_sync(0xffffffffu, ss, o);
    }
    if (lane == 0) { sb[wid] = s; ssb[wid] = ss; }
    __syncthreads();
    if (tid == 0) {
        float ts = 0.f, tss = 0.f;
        #pragma unroll
        for (int i = 0; i < 8; i++) { ts += sb[i]; tss += ssb[i]; }
        float mean = ts * (1.f / 1024.f);
        sb[0]  = mean;
        ssb[0] = rsqrtf(tss * (1.f / 1024.f) - mean * mean + EPSF);
    }
    __syncthreads();
    const float mean = sb[0], rstd = ssb[0];
    const float4 wv = reinterpret_cast<const float4*>(w)[tid];
    const float4 bv = reinterpret_cast<const float4*>(b)[tid];
    float4 o;
    o.x = to_tf32((xv.x - mean) * rstd * wv.x + bv.x);
    o.y = to_tf32((xv.y - mean) * rstd * wv.y + bv.y);
    o.z = to_tf32((xv.z - mean) * rstd * wv.z + bv.z);
    o.w = to_tf32((xv.w - mean) * rstd * wv.w + bv.w);
    reinterpret_cast<float4*>(out + (size_t)row * 1024)[tid] = o;
}

// ============================================================
// Per-head LN (hd=64) on q and k slices of the qkv buffer.
// ============================================================
__global__ void headln_kernel(float* __restrict__ qkv, const float* __restrict__ w,
                              const float* __restrict__ b, float qscale)
{
    const int gw   = (blockIdx.x * blockDim.x + threadIdx.x) >> 5;
    const int lane = threadIdx.x & 31;
    const int r     = gw >> 5;
    const int rem   = gw & 31;
    const int which = rem >> 4;
    const int h     = rem & 15;
    float* p = qkv + (size_t)r * 3072 + which * 1024 + h * 64;
    const float v0 = p[lane], v1 = p[lane + 32];
    float s = v0 + v1, ss = v0*v0 + v1*v1;
    #pragma unroll
    for (int o = 16; o; o >>= 1) {
        s  += __shfl_xor_sync(0xffffffffu, s,  o);
        ss += __shfl_xor_sync(0xffffffffu, ss, o);
    }
    const float mean = s * (1.f / 64.f);
    const float rstd = rsqrtf(ss * (1.f / 64.f) - mean * mean + EPSF);
    const float sc = which ? 1.f : qscale;
    p[lane]      = ((v0 - mean) * rstd * w[lane]      + b[lane])      * sc;
    p[lane + 32] = ((v1 - mean) * rstd * w[lane + 32] + b[lane + 32]) * sc;
}

// ============================================================
// Spatial attention (N=256), single pass, fixed-shift softmax
// ============================================================
__global__ void attn_kernel(const float* __restrict__ qkv, float* __restrict__ out)
{
    constexpr int N = 256;
    extern __shared__ float sm[];
    float* Ks = sm;
    float* Vs = sm + N * 64;
    const int bh = blockIdx.x;
    const int h = bh & 15;
    const int batch = bh >> 4;
    const float* base = qkv + (size_t)batch * N * 3072;
    const int tid = threadIdx.x;

    for (int idx = tid; idx < N * 16; idx += N) {
        const int j = idx >> 4, d4 = idx & 15;
        const float4* kp = reinterpret_cast<const float4*>(base + (size_t)j * 3072 + 1024 + h * 64);
        const float4* vp = reinterpret_cast<const float4*>(base + (size_t)j * 3072 + 2048 + h * 64);
        reinterpret_cast<float4*>(Ks + j * 64)[d4] = kp[d4];
        reinterpret_cast<float4*>(Vs + j * 64)[d4] = vp[d4];
    }
    __syncthreads();

    float4 q[16];
    const float4* qp = reinterpret_cast<const float4*>(base + (size_t)tid * 3072 + h * 64);
    #pragma unroll
    for (int d = 0; d < 16; d++) q[d] = qp[d];

    float4 acc[16];
    #pragma unroll
    for (int d = 0; d < 16; d++) acc[d] = make_float4(0.f, 0.f, 0.f, 0.f);
    float sum = 0.f;
    for (int j = 0; j < N; j++) {
        const float4* kr = reinterpret_cast<const float4*>(Ks + j * 64);
        float s = 0.f;
        #pragma unroll
        for (int d = 0; d < 16; d++) {
            const float4 kv = kr[d];
            s += q[d].x*kv.x + q[d].y*kv.y + q[d].z*kv.z + q[d].w*kv.w;
        }
        const float e = __expf(s - ESHIFT);
        sum += e;
        const float4* vr = reinterpret_cast<const float4*>(Vs + j * 64);
        #pragma unroll
        for (int d = 0; d < 16; d++) {
            const float4 vv = vr[d];
            acc[d].x += e * vv.x; acc[d].y += e * vv.y;
            acc[d].z += e * vv.z; acc[d].w += e * vv.w;
        }
    }
    const float inv = 1.f / sum;
    float4* op = reinterpret_cast<float4*>(out + ((size_t)batch * N + tid) * 1024 + h * 64);
    #pragma unroll
    for (int d = 0; d < 16; d++)
        op[d] = make_float4(to_tf32(acc[d].x * inv), to_tf32(acc[d].y * inv),
                            to_tf32(acc[d].z * inv), to_tf32(acc[d].w * inv));
}

// ============================================================
// Temporal attention (N=16): 256-thread blocks, 16 groups/block
// ============================================================
__global__ void attn16_kernel(const float* __restrict__ qkv, float* __restrict__ out)
{
    constexpr int N = 16;
    const int tid = threadIdx.x;
    const int bh = blockIdx.x * 16 + (tid >> 4);
    const int h = bh & 15;
    const int batch = bh >> 4;
    const int row = tid & 15;
    const float* base = qkv + (size_t)batch * N * 3072;

    float4 q[16];
    const float4* qp = reinterpret_cast<const float4*>(base + (size_t)row * 3072 + h * 64);
    #pragma unroll
    for (int d = 0; d < 16; d++) q[d] = qp[d];

    float4 acc[16];
    #pragma unroll
    for (int d = 0; d < 16; d++) acc[d] = make_float4(0.f, 0.f, 0.f, 0.f);
    float sum = 0.f;
    #pragma unroll
    for (int j = 0; j < N; j++) {
        const float4* kr = reinterpret_cast<const float4*>(base + (size_t)j * 3072 + 1024 + h * 64);
        float s = 0.f;
        #pragma unroll
        for (int d = 0; d < 16; d++) {
            const float4 kv = kr[d];
            s += q[d].x*kv.x + q[d].y*kv.y + q[d].z*kv.z + q[d].w*kv.w;
        }
        const float e = __expf(s - ESHIFT);
        sum += e;
        const float4* vr = reinterpret_cast<const float4*>(base + (size_t)j * 3072 + 2048 + h * 64);
        #pragma unroll
        for (int d = 0; d < 16; d++) {
            const float4 vv = vr[d];
            acc[d].x += e * vv.x; acc[d].y += e * vv.y;
            acc[d].z += e * vv.z; acc[d].w += e * vv.w;
        }
    }
    const float inv = 1.f / sum;
    float4* op = reinterpret_cast<float4*>(out + ((size_t)batch * N + row) * 1024 + h * 64);
    #pragma unroll
    for (int d = 0; d < 16; d++)
        op[d] = make_float4(to_tf32(acc[d].x * inv), to_tf32(acc[d].y * inv),
                            to_tf32(acc[d].z * inv), to_tf32(acc[d].w * inv));
}

// ============================================================
// (B,T,S,C) <-> (B,S,T,C) row permutation
// ============================================================
__global__ void permute_kernel(const float* __restrict__ src, float* __restrict__ dst, int fwd)
{
    const int rt = blockIdx.x;
    int in_row;
    if (fwd) {
        const int t = rt & 15;  const int bs = rt >> 4;
        const int s = bs & 255; const int b  = bs >> 8;
        in_row = (b * 16 + t) * 256 + s;
    } else {
        const int s = rt & 255; const int bt = rt >> 8;
        const int t = bt & 15;  const int b  = bt >> 4;
        in_row = (b * 256 + s) * 16 + t;
    }
    const float4* sp = reinterpret_cast<const float4*>(src + (size_t)in_row * 1024);
    float4* dp = reinterpret_cast<float4*>(dst + (size_t)rt * 1024);
    dp[threadIdx.x] = sp[threadIdx.x];
}

// ============================================================
// Tensor-core GEMM via mma.sync (tf32) + ldmatrix:
//   C[M,N] = A[M,K] @ Bt[N,K]^T  (+bias)(+resid)(+gelu)(+round)
// 128x128 tile per CTA, BK=32, TWO-stage cp.async pipeline (R3 struct).
// XOR-swizzled packed smem (128 rows x 128B, chunk c' = c ^ (r&7)),
// 16KB/tile, 64KB/CTA -> 2 CTAs/SM.
// Fragments loaded with ldmatrix.m8n8.x4.b16 (conflict-free phases).
// ============================================================
constexpr int STG_B    = 32768;           // bytes per stage (A 16KB + B 16KB)
constexpr int GEMM_SMEM = 2 * STG_B;      // 65536 B

template<bool GELU, bool ROUND>
__global__ __launch_bounds__(256, 2) void gemm_mma(
    const float* __restrict__ A, const float* __restrict__ Bt,
    float* __restrict__ Cm, const float* __restrict__ bias,
    const float* __restrict__ resid, int M, int N, int K)
{
    extern __shared__ float sm[];
    const uint32_t stg = smem_u32(sm);

    const int tid = threadIdx.x;
    const int wid = tid >> 5, lane = tid & 31;
    const int g = lane >> 2, tig = lane & 3;     // mma fragment coords
    const int warpM = wid & 3, warpN = wid >> 2; // 4x2 warp grid
    const int bx = blockIdx.x, by = blockIdx.y;
    const int NKB = K >> 5;

    // ---- cp.async assignments: 4 chunks of 16B for A, 4 for B (swizzled dst)
    uint32_t a_s[4], b_s[4];
    const float *a_g[4], *b_g[4];
    #pragma unroll
    for (int t = 0; t < 4; t++) {
        const int idx = tid + (t << 8);          // 0..1023
        const int r = idx >> 3, c = idx & 7;     // row, 16B k-chunk
        const uint32_t sw = (uint32_t)(r * 128 + ((c ^ (r & 7)) << 4));
        a_s[t] = sw;            b_s[t] = sw + 16384;
        a_g[t] = A  + (size_t)(by * 128 + r) * K + c * 4;
        b_g[t] = Bt + (size_t)(bx * 128 + r) * K + c * 4;
    }

    auto load_stage = [&](int s, int kb) {
        const uint32_t sb = stg + s * STG_B;
        const int ko = kb << 5;
        #pragma unroll
        for (int t = 0; t < 4; t++)
            asm volatile("cp.async.cg.shared.global [%0], [%1], 16;" ::
                "r"(sb + a_s[t]), "l"(a_g[t] + ko) : "memory");
        #pragma unroll
        for (int t = 0; t < 4; t++)
            asm volatile("cp.async.cg.shared.global [%0], [%1], 16;" ::
                "r"(sb + b_s[t]), "l"(b_g[t] + ko) : "memory");
    };

    // ---- ldmatrix per-lane addressing (within tile) ----
    // A x4 (per mt): lanes q=lane>>3: q0: rows base+0..7 chunk 2ks; q1: rows+8 chunk 2ks;
    //                q2: rows base chunk 2ks+1; q3: rows+8 chunk 2ks+1.
    const int lr = lane & 7;
    const int aRow = warpM * 32 + ((lane >> 3) & 1) * 8 + lr;   // + mt*16
    const int cbA  = lane >> 4;                                 // chunk LSB
    const uint32_t aRx = (uint32_t)(aRow * 128);
    const uint32_t a7  = (uint32_t)(aRow & 7);
    // B x4 (per ntp): q0: rows n0..7 chunk 2ks; q1: rows n0..7 chunk 2ks+1;
    //                 q2: rows+8 chunk 2ks; q3: rows+8 chunk 2ks+1.
    const int bRow = warpN * 64 + (lane >> 4) * 8 + lr;         // + ntp*16
    const int cbB  = (lane >> 3) & 1;
    const uint32_t bRx = (uint32_t)(bRow * 128);
    const uint32_t b7  = (uint32_t)(bRow & 7);

    float acc[2][8][4];
    #pragma unroll
    for (int mt = 0; mt < 2; mt++)
        #pragma unroll
        for (int nt = 0; nt < 8; nt++)
            #pragma unroll
            for (int i = 0; i < 4; i++) acc[mt][nt][i] = 0.f;

    load_stage(0, 0);
    asm volatile("cp.async.commit_group;" ::: "memory");

    for (int kb = 0; kb < NKB; kb++) {
        if (kb + 1 < NKB) {
            load_stage((kb + 1) & 1, kb + 1);
            asm volatile("cp.async.commit_group;" ::: "memory");
            asm volatile("cp.async.wait_group 1;" ::: "memory");
        } else {
            asm volatile("cp.async.wait_group 0;" ::: "memory");
        }
        __syncthreads();

        const uint32_t sA = stg + (kb & 1) * STG_B;
        const uint32_t sB = sA + 16384;
        #pragma unroll
        for (int ks = 0; ks < 4; ks++) {
            uint32_t a[2][4], b[8][2];
            const uint32_t swA = ((uint32_t)(2 * ks + cbA) ^ a7) << 4;
            #pragma unroll
            for (int mt = 0; mt < 2; mt++)
                ldsm4(a[mt][0], a[mt][1], a[mt][2], a[mt][3],
                      sA + aRx + (uint32_t)(mt * 16 * 128) + swA);
            const uint32_t swB = ((uint32_t)(2 * ks + cbB) ^ b7) << 4;
            #pragma unroll
            for (int ntp = 0; ntp < 4; ntp++)
                ldsm4(b[2 * ntp][0], b[2 * ntp][1], b[2 * ntp + 1][0], b[2 * ntp + 1][1],
                      sB + bRx + (uint32_t)(ntp * 16 * 128) + swB);
            #pragma unroll
            for (int mt = 0; mt < 2; mt++)
                #pragma unroll
                for (int nt = 0; nt < 8; nt++)
                    mma_tf32(acc[mt][nt], a[mt], b[nt]);
        }
        __syncthreads();
    }

    // ---- epilogue ----
    #pragma unroll
    for (int mt = 0; mt < 2; mt++) {
        #pragma unroll
        for (int half = 0; half < 2; half++) {
            const int row = by * 128 + warpM * 32 + mt * 16 + g + half * 8;
            float* cp = Cm + (size_t)row * N;
            const float* rp = resid ? resid + (size_t)row * N : nullptr;
            #pragma unroll
            for (int nt = 0; nt < 8; nt++) {
                const int col = bx * 128 + warpN * 64 + nt * 8 + tig * 2;
                float v0 = acc[mt][nt][half * 2 + 0];
                float v1 = acc[mt][nt][half * 2 + 1];
                if (bias) { v0 += bias[col]; v1 += bias[col + 1]; }
                if (rp)   { v0 += rp[col];   v1 += rp[col + 1]; }
                if (GELU) {
                    v0 = 0.5f * v0 * (1.f + erff(v0 * 0.70710678f));
                    v1 = 0.5f * v1 * (1.f + erff(v1 * 0.70710678f));
                }
                if (ROUND) { v0 = to_tf32(v0); v1 = to_tf32(v1); }
                float2 v; v.x = v0; v.y = v1;
                *reinterpret_cast<float2*>(cp + col) = v;
            }
        }
    }
}

// ============================================================
extern "C" void kernel_launch(void* const* d_in, const int* /*in_sizes*/, int /*n_in*/,
                              void* d_out, int /*out_size*/)
{
    const float* x        = (const float*)d_in[0];
    const float* ns_w     = (const float*)d_in[1];
    const float* ns_b     = (const float*)d_in[2];
    const float* nt_w     = (const float*)d_in[3];
    const float* nt_b     = (const float*)d_in[4];
    const float* nm_w     = (const float*)d_in[5];
    const float* nm_b     = (const float*)d_in[6];
    const float* s_qkv    = (const float*)d_in[7];
    const float* s_qkn_w  = (const float*)d_in[8];
    const float* s_qkn_b  = (const float*)d_in[9];
    const float* s_proj_w = (const float*)d_in[10];
    const float* s_proj_b = (const float*)d_in[11];
    const float* t_qkv    = (const float*)d_in[12];
    const float* t_qkn_w  = (const float*)d_in[13];
    const float* t_qkn_b  = (const float*)d_in[14];
    const float* t_proj_w = (const float*)d_in[15];
    const float* t_proj_b = (const float*)d_in[16];
    const float* fc1_w    = (const float*)d_in[17];
    const float* fc1_b    = (const float*)d_in[18];
    const float* fc2_w    = (const float*)d_in[19];
    const float* fc2_b    = (const float*)d_in[20];
    float* out = (float*)d_out;

    float *xbuf, *xln, *qkv, *attn, *xt, *hbuf;
    float *wt_sqkv, *wt_sproj, *wt_tqkv, *wt_tproj, *wt_fc1, *wt_fc2;
    cudaGetSymbolAddress((void**)&xbuf, g_xbuf);
    cudaGetSymbolAddress((void**)&xln,  g_xln);
    cudaGetSymbolAddress((void**)&qkv,  g_qkv);
    cudaGetSymbolAddress((void**)&attn, g_attn);
    cudaGetSymbolAddress((void**)&xt,   g_xt);
    cudaGetSymbolAddress((void**)&hbuf, g_h);
    cudaGetSymbolAddress((void**)&wt_sqkv,  g_wt_sqkv);
    cudaGetSymbolAddress((void**)&wt_sproj, g_wt_sproj);
    cudaGetSymbolAddress((void**)&wt_tqkv,  g_wt_tqkv);
    cudaGetSymbolAddress((void**)&wt_tproj, g_wt_tproj);
    cudaGetSymbolAddress((void**)&wt_fc1,   g_wt_fc1);
    cudaGetSymbolAddress((void**)&wt_fc2,   g_wt_fc2);

    cudaFuncSetAttribute(attn_kernel, cudaFuncAttributeMaxDynamicSharedMemorySize,
                         256 * 64 * 2 * (int)sizeof(float));
    cudaFuncSetAttribute(gemm_mma<false, false>, cudaFuncAttributeMaxDynamicSharedMemorySize, GEMM_SMEM);
    cudaFuncSetAttribute(gemm_mma<true,  true >, cudaFuncAttributeMaxDynamicSharedMemorySize, GEMM_SMEM);

    // ---- weight transposes (+ tf32 rounding), once per launch ----
    dim3 tb(32, 8);
    transpose_w<<<dim3(3072/32, 1024/32), tb>>>(s_qkv,    wt_sqkv,  1024, 3072);
    transpose_w<<<dim3(1024/32, 1024/32), tb>>>(s_proj_w, wt_sproj, 1024, 1024);
    transpose_w<<<dim3(3072/32, 1024/32), tb>>>(t_qkv,    wt_tqkv,  1024, 3072);
    transpose_w<<<dim3(1024/32, 1024/32), tb>>>(t_proj_w, wt_tproj, 1024, 1024);
    transpose_w<<<dim3(4096/32, 1024/32), tb>>>(fc1_w,    wt_fc1,   1024, 4096);
    transpose_w<<<dim3(1024/32, 4096/32), tb>>>(fc2_w,    wt_fc2,   4096, 1024);

    const int hl_blocks = (R_ * 2 * H_) / 8;

    // ---- spatial attention block ----
    ln_kernel<<<R_, 256>>>(x, xln, ns_w, ns_b);
    gemm_mma<false, false><<<dim3(24, 64), 256, GEMM_SMEM>>>(xln, wt_sqkv, qkv, nullptr, nullptr, R_, 3072, 1024);
    headln_kernel<<<hl_blocks, 256>>>(qkv, s_qkn_w, s_qkn_b, SCALE_);
    attn_kernel<<<B_ * T_ * H_, 256, 256 * 64 * 2 * sizeof(float)>>>(qkv, attn);
    gemm_mma<false, false><<<dim3(8, 64), 256, GEMM_SMEM>>>(attn, wt_sproj, xbuf, s_proj_b, x, R_, 1024, 1024);

    // ---- temporal attention block ----
    permute_kernel<<<R_, 256>>>(xbuf, xt, 1);
    ln_kernel<<<R_, 256>>>(xt, xln, nt_w, nt_b);
    gemm_mma<false, false><<<dim3(24, 64), 256, GEMM_SMEM>>>(xln, wt_tqkv, qkv, nullptr, nullptr, R_, 3072, 1024);
    headln_kernel<<<hl_blocks, 256>>>(qkv, t_qkn_w, t_qkn_b, SCALE_);
    attn16_kernel<<<(B_ * S_ * H_) / 16, 256>>>(qkv, attn);
    gemm_mma<false, false><<<dim3(8, 64), 256, GEMM_SMEM>>>(attn, wt_tproj, xln, t_proj_b, xt, R_, 1024, 1024);
    permute_kernel<<<R_, 256>>>(xln, xbuf, 0);

    // ---- MLP ----
    ln_kernel<<<R_, 256>>>(xbuf, xln, nm_w, nm_b);
    gemm_mma<true,  true ><<<dim3(32, 64), 256, GEMM_SMEM>>>(xln, wt_fc1, hbuf, fc1_b, nullptr, R_, 4096, 1024);
    gemm_mma<false, false><<<dim3(8, 64), 256, GEMM_SMEM>>>(hbuf, wt_fc2, out, fc2_b, xbuf, R_, 1024, 4096);
}

// round 6
// speedup vs baseline: 1.8543x; 1.0046x over previous
#include <cuda_runtime.h>
#include <cstdint>
#include <math.h>

#define EPSF 1e-5f

constexpr int B_  = 2, T_ = 16, S_ = 256, C_ = 1024, H_ = 16;
constexpr int R_  = B_ * T_ * S_;   // 8192 tokens
constexpr int HID_ = 4 * C_;        // 4096
constexpr float SCALE_ = 8.0f / 64.0f;

// ---- scratch (device globals; no runtime allocation allowed) ----
__device__ float g_xbuf[R_ * C_];
__device__ float g_xln [R_ * C_];
__device__ float g_qkv [R_ * 3 * C_];
__device__ float g_attn[R_ * C_];
__device__ float g_h   [R_ * HID_];
// transposed (tf32-rounded) weights, [N,K] row-major
__device__ float g_wt_sqkv [3 * C_ * C_];
__device__ float g_wt_sproj[C_ * C_];
__device__ float g_wt_tqkv [3 * C_ * C_];
__device__ float g_wt_tproj[C_ * C_];
__device__ float g_wt_fc1  [HID_ * C_];
__device__ float g_wt_fc2  [C_ * HID_];

__device__ __forceinline__ uint32_t smem_u32(const void* p) {
    uint32_t a;
    asm("{ .reg .u64 t; cvta.to.shared.u64 t, %1; cvt.u32.u64 %0, t; }" : "=r"(a) : "l"(p));
    return a;
}
__device__ __forceinline__ float to_tf32(float x) {
    float r;
    asm("cvt.rna.tf32.f32 %0, %1;" : "=f"(r) : "f"(x));
    return r;
}
// e^(s-8) entirely on fma/alu pipes (no MUFU). Valid for s in [-40, 40].
__device__ __forceinline__ float fexp_shift(float s) {
    const float y = fmaf(s, 1.44269504089f, -11.5415603272f);  // (s-8)*log2e
    const int   i = __float2int_rn(y);
    const float f = y - (float)i;                               // [-0.5, 0.5]
    float p = fmaf(f, 0.00133335581f, 0.00961812910f);
    p = fmaf(f, p, 0.0555041087f);
    p = fmaf(f, p, 0.240226507f);
    p = fmaf(f, p, 0.693147181f);
    p = fmaf(f, p, 1.0f);                                       // 2^f
    return __int_as_float(__float_as_int(p) + (i << 23));
}
__device__ __forceinline__ void ldsm4(uint32_t& r0, uint32_t& r1, uint32_t& r2,
                                      uint32_t& r3, uint32_t addr) {
    asm volatile("ldmatrix.sync.aligned.m8n8.x4.b16 {%0,%1,%2,%3}, [%4];"
        : "=r"(r0), "=r"(r1), "=r"(r2), "=r"(r3) : "r"(addr));
}
__device__ __forceinline__ void mma_tf32(float c[4], const uint32_t a[4], const uint32_t b[2]) {
    asm volatile("mma.sync.aligned.m16n8k8.row.col.f32.tf32.tf32.f32 "
        "{%0,%1,%2,%3}, {%4,%5,%6,%7}, {%8,%9}, {%0,%1,%2,%3};"
        : "+f"(c[0]), "+f"(c[1]), "+f"(c[2]), "+f"(c[3])
        : "r"(a[0]), "r"(a[1]), "r"(a[2]), "r"(a[3]), "r"(b[0]), "r"(b[1]));
}

// ============================================================
// Weight transpose + tf32 round: in [K,N] -> out [N,K]
// ============================================================
__global__ void transpose_w(const float* __restrict__ in, float* __restrict__ out,
                            int K, int N)
{
    __shared__ float t[32][33];
    const int n0 = blockIdx.x * 32, k0 = blockIdx.y * 32;
    const int x = threadIdx.x, y = threadIdx.y;
    #pragma unroll
    for (int i = 0; i < 32; i += 8)
        t[y + i][x] = in[(size_t)(k0 + y + i) * N + n0 + x];
    __syncthreads();
    #pragma unroll
    for (int i = 0; i < 32; i += 8)
        out[(size_t)(n0 + y + i) * K + k0 + x] = to_tf32(t[x][y + i]);
}

// ============================================================
// LayerNorm over C=1024. PERM: gather input row through the
// (B,T,S)->(B,S,T) map (replaces the standalone permute pass).
// ============================================================
template<bool PERM>
__global__ void ln_kernel(const float* __restrict__ in, float* __restrict__ out,
                          const float* __restrict__ w, const float* __restrict__ b)
{
    const int row = blockIdx.x, tid = threadIdx.x;
    int in_row = row;
    if (PERM) {
        const int t = row & 15, s = (row >> 4) & 255, bb = row >> 12;
        in_row = bb * 4096 + t * 256 + s;   // spatial-order source row
    }
    const float4 xv = reinterpret_cast<const float4*>(in + (size_t)in_row * 1024)[tid];
    float s  = xv.x + xv.y + xv.z + xv.w;
    float ss = xv.x*xv.x + xv.y*xv.y + xv.z*xv.z + xv.w*xv.w;
    __shared__ float sb[32], ssb[32];
    const int lane = tid & 31, wid = tid >> 5;
    #pragma unroll
    for (int o = 16; o; o >>= 1) {
        s  += __shfl_xor_sync(0xffffffffu, s,  o);
        ss += __shfl_xor_sync(0xffffffffu, ss, o);
    }
    if (lane == 0) { sb[wid] = s; ssb[wid] = ss; }
    __syncthreads();
    if (tid == 0) {
        float ts = 0.f, tss = 0.f;
        #pragma unroll
        for (int i = 0; i < 8; i++) { ts += sb[i]; tss += ssb[i]; }
        float mean = ts * (1.f / 1024.f);
        sb[0]  = mean;
        ssb[0] = rsqrtf(tss * (1.f / 1024.f) - mean * mean + EPSF);
    }
    __syncthreads();
    const float mean = sb[0], rstd = ssb[0];
    const float4 wv = reinterpret_cast<const float4*>(w)[tid];
    const float4 bv = reinterpret_cast<const float4*>(b)[tid];
    float4 o;
    o.x = to_tf32((xv.x - mean) * rstd * wv.x + bv.x);
    o.y = to_tf32((xv.y - mean) * rstd * wv.y + bv.y);
    o.z = to_tf32((xv.z - mean) * rstd * wv.z + bv.z);
    o.w = to_tf32((xv.w - mean) * rstd * wv.w + bv.w);
    reinterpret_cast<float4*>(out + (size_t)row * 1024)[tid] = o;
}

// ============================================================
// Per-head LN (hd=64) on q and k slices of the qkv buffer.
// ============================================================
__global__ void headln_kernel(float* __restrict__ qkv, const float* __restrict__ w,
                              const float* __restrict__ b, float qscale)
{
    const int gw   = (blockIdx.x * blockDim.x + threadIdx.x) >> 5;
    const int lane = threadIdx.x & 31;
    const int r     = gw >> 5;
    const int rem   = gw & 31;
    const int which = rem >> 4;
    const int h     = rem & 15;
    float* p = qkv + (size_t)r * 3072 + which * 1024 + h * 64;
    const float v0 = p[lane], v1 = p[lane + 32];
    float s = v0 + v1, ss = v0*v0 + v1*v1;
    #pragma unroll
    for (int o = 16; o; o >>= 1) {
        s  += __shfl_xor_sync(0xffffffffu, s,  o);
        ss += __shfl_xor_sync(0xffffffffu, ss, o);
    }
    const float mean = s * (1.f / 64.f);
    const float rstd = rsqrtf(ss * (1.f / 64.f) - mean * mean + EPSF);
    const float sc = which ? 1.f : qscale;
    p[lane]      = ((v0 - mean) * rstd * w[lane]      + b[lane])      * sc;
    p[lane + 32] = ((v1 - mean) * rstd * w[lane + 32] + b[lane + 32]) * sc;
}

// ============================================================
// Spatial attention (N=256), single pass, fixed-shift FMA exp
// ============================================================
__global__ void attn_kernel(const float* __restrict__ qkv, float* __restrict__ out)
{
    constexpr int N = 256;
    extern __shared__ float sm[];
    float* Ks = sm;
    float* Vs = sm + N * 64;
    const int bh = blockIdx.x;
    const int h = bh & 15;
    const int batch = bh >> 4;
    const float* base = qkv + (size_t)batch * N * 3072;
    const int tid = threadIdx.x;

    for (int idx = tid; idx < N * 16; idx += N) {
        const int j = idx >> 4, d4 = idx & 15;
        const float4* kp = reinterpret_cast<const float4*>(base + (size_t)j * 3072 + 1024 + h * 64);
        const float4* vp = reinterpret_cast<const float4*>(base + (size_t)j * 3072 + 2048 + h * 64);
        reinterpret_cast<float4*>(Ks + j * 64)[d4] = kp[d4];
        reinterpret_cast<float4*>(Vs + j * 64)[d4] = vp[d4];
    }
    __syncthreads();

    float4 q[16];
    const float4* qp = reinterpret_cast<const float4*>(base + (size_t)tid * 3072 + h * 64);
    #pragma unroll
    for (int d = 0; d < 16; d++) q[d] = qp[d];

    float4 acc[16];
    #pragma unroll
    for (int d = 0; d < 16; d++) acc[d] = make_float4(0.f, 0.f, 0.f, 0.f);
    float sum = 0.f;
    #pragma unroll 2
    for (int j = 0; j < N; j++) {
        const float4* kr = reinterpret_cast<const float4*>(Ks + j * 64);
        float s = 0.f;
        #pragma unroll
        for (int d = 0; d < 16; d++) {
            const float4 kv = kr[d];
            s += q[d].x*kv.x + q[d].y*kv.y + q[d].z*kv.z + q[d].w*kv.w;
        }
        const float e = fexp_shift(s);
        sum += e;
        const float4* vr = reinterpret_cast<const float4*>(Vs + j * 64);
        #pragma unroll
        for (int d = 0; d < 16; d++) {
            const float4 vv = vr[d];
            acc[d].x += e * vv.x; acc[d].y += e * vv.y;
            acc[d].z += e * vv.z; acc[d].w += e * vv.w;
        }
    }
    const float inv = 1.f / sum;
    float4* op = reinterpret_cast<float4*>(out + ((size_t)batch * N + tid) * 1024 + h * 64);
    #pragma unroll
    for (int d = 0; d < 16; d++)
        op[d] = make_float4(to_tf32(acc[d].x * inv), to_tf32(acc[d].y * inv),
                            to_tf32(acc[d].z * inv), to_tf32(acc[d].w * inv));
}

// ============================================================
// Temporal attention (N=16): 256-thread blocks, 16 groups/block
// ============================================================
__global__ void attn16_kernel(const float* __restrict__ qkv, float* __restrict__ out)
{
    constexpr int N = 16;
    const int tid = threadIdx.x;
    const int bh = blockIdx.x * 16 + (tid >> 4);
    const int h = bh & 15;
    const int batch = bh >> 4;
    const int row = tid & 15;
    const float* base = qkv + (size_t)batch * N * 3072;

    float4 q[16];
    const float4* qp = reinterpret_cast<const float4*>(base + (size_t)row * 3072 + h * 64);
    #pragma unroll
    for (int d = 0; d < 16; d++) q[d] = qp[d];

    float4 acc[16];
    #pragma unroll
    for (int d = 0; d < 16; d++) acc[d] = make_float4(0.f, 0.f, 0.f, 0.f);
    float sum = 0.f;
    #pragma unroll
    for (int j = 0; j < N; j++) {
        const float4* kr = reinterpret_cast<const float4*>(base + (size_t)j * 3072 + 1024 + h * 64);
        float s = 0.f;
        #pragma unroll
        for (int d = 0; d < 16; d++) {
            const float4 kv = kr[d];
            s += q[d].x*kv.x + q[d].y*kv.y + q[d].z*kv.z + q[d].w*kv.w;
        }
        const float e = fexp_shift(s);
        sum += e;
        const float4* vr = reinterpret_cast<const float4*>(base + (size_t)j * 3072 + 2048 + h * 64);
        #pragma unroll
        for (int d = 0; d < 16; d++) {
            const float4 vv = vr[d];
            acc[d].x += e * vv.x; acc[d].y += e * vv.y;
            acc[d].z += e * vv.z; acc[d].w += e * vv.w;
        }
    }
    const float inv = 1.f / sum;
    float4* op = reinterpret_cast<float4*>(out + ((size_t)batch * N + row) * 1024 + h * 64);
    #pragma unroll
    for (int d = 0; d < 16; d++)
        op[d] = make_float4(to_tf32(acc[d].x * inv), to_tf32(acc[d].y * inv),
                            to_tf32(acc[d].z * inv), to_tf32(acc[d].w * inv));
}

// ============================================================
// Tensor-core GEMM via mma.sync (tf32) + ldmatrix:
//   C[M,N] = A[M,K] @ Bt[N,K]^T  (+bias)(+resid)(+gelu)(+round)
// PERMROW: scatter output rows (and gather residual) through the
// (B,S,T)->(B,T,S) map (fuses the inverse permute).
// ============================================================
constexpr int STG_B    = 32768;           // bytes per stage (A 16KB + B 16KB)
constexpr int GEMM_SMEM = 2 * STG_B;      // 65536 B

template<bool GELU, bool ROUND, bool PERMROW>
__global__ __launch_bounds__(256, 2) void gemm_mma(
    const float* __restrict__ A, const float* __restrict__ Bt,
    float* __restrict__ Cm, const float* __restrict__ bias,
    const float* __restrict__ resid, int M, int N, int K)
{
    extern __shared__ float sm[];
    const uint32_t stg = smem_u32(sm);

    const int tid = threadIdx.x;
    const int wid = tid >> 5, lane = tid & 31;
    const int g = lane >> 2, tig = lane & 3;     // mma fragment coords
    const int warpM = wid & 3, warpN = wid >> 2; // 4x2 warp grid
    const int bx = blockIdx.x, by = blockIdx.y;
    const int NKB = K >> 5;

    // ---- cp.async assignments: 4 chunks of 16B for A, 4 for B (swizzled dst)
    uint32_t a_s[4], b_s[4];
    const float *a_g[4], *b_g[4];
    #pragma unroll
    for (int t = 0; t < 4; t++) {
        const int idx = tid + (t << 8);          // 0..1023
        const int r = idx >> 3, c = idx & 7;     // row, 16B k-chunk
        const uint32_t sw = (uint32_t)(r * 128 + ((c ^ (r & 7)) << 4));
        a_s[t] = sw;            b_s[t] = sw + 16384;
        a_g[t] = A  + (size_t)(by * 128 + r) * K + c * 4;
        b_g[t] = Bt + (size_t)(bx * 128 + r) * K + c * 4;
    }

    auto load_stage = [&](int s, int kb) {
        const uint32_t sb = stg + s * STG_B;
        const int ko = kb << 5;
        #pragma unroll
        for (int t = 0; t < 4; t++)
            asm volatile("cp.async.cg.shared.global [%0], [%1], 16;" ::
                "r"(sb + a_s[t]), "l"(a_g[t] + ko) : "memory");
        #pragma unroll
        for (int t = 0; t < 4; t++)
            asm volatile("cp.async.cg.shared.global [%0], [%1], 16;" ::
                "r"(sb + b_s[t]), "l"(b_g[t] + ko) : "memory");
    };

    // ---- ldmatrix per-lane addressing (within tile) ----
    const int lr = lane & 7;
    const int aRow = warpM * 32 + ((lane >> 3) & 1) * 8 + lr;   // + mt*16
    const int cbA  = lane >> 4;
    const uint32_t aRx = (uint32_t)(aRow * 128);
    const uint32_t a7  = (uint32_t)(aRow & 7);
    const int bRow = warpN * 64 + (lane >> 4) * 8 + lr;         // + ntp*16
    const int cbB  = (lane >> 3) & 1;
    const uint32_t bRx = (uint32_t)(bRow * 128);
    const uint32_t b7  = (uint32_t)(bRow & 7);

    float acc[2][8][4];
    #pragma unroll
    for (int mt = 0; mt < 2; mt++)
        #pragma unroll
        for (int nt = 0; nt < 8; nt++)
            #pragma unroll
            for (int i = 0; i < 4; i++) acc[mt][nt][i] = 0.f;

    load_stage(0, 0);
    asm volatile("cp.async.commit_group;" ::: "memory");

    for (int kb = 0; kb < NKB; kb++) {
        if (kb + 1 < NKB) {
            load_stage((kb + 1) & 1, kb + 1);
            asm volatile("cp.async.commit_group;" ::: "memory");
            asm volatile("cp.async.wait_group 1;" ::: "memory");
        } else {
            asm volatile("cp.async.wait_group 0;" ::: "memory");
        }
        __syncthreads();

        const uint32_t sA = stg + (kb & 1) * STG_B;
        const uint32_t sB = sA + 16384;
        #pragma unroll
        for (int ks = 0; ks < 4; ks++) {
            uint32_t a[2][4], b[8][2];
            const uint32_t swA = ((uint32_t)(2 * ks + cbA) ^ a7) << 4;
            #pragma unroll
            for (int mt = 0; mt < 2; mt++)
                ldsm4(a[mt][0], a[mt][1], a[mt][2], a[mt][3],
                      sA + aRx + (uint32_t)(mt * 16 * 128) + swA);
            const uint32_t swB = ((uint32_t)(2 * ks + cbB) ^ b7) << 4;
            #pragma unroll
            for (int ntp = 0; ntp < 4; ntp++)
                ldsm4(b[2 * ntp][0], b[2 * ntp][1], b[2 * ntp + 1][0], b[2 * ntp + 1][1],
                      sB + bRx + (uint32_t)(ntp * 16 * 128) + swB);
            #pragma unroll
            for (int mt = 0; mt < 2; mt++)
                #pragma unroll
                for (int nt = 0; nt < 8; nt++)
                    mma_tf32(acc[mt][nt], a[mt], b[nt]);
        }
        __syncthreads();
    }

    // ---- epilogue ----
    #pragma unroll
    for (int mt = 0; mt < 2; mt++) {
        #pragma unroll
        for (int half = 0; half < 2; half++) {
            int row = by * 128 + warpM * 32 + mt * 16 + g + half * 8;
            if (PERMROW) {
                const int t = row & 15, s = (row >> 4) & 255, bb = row >> 12;
                row = bb * 4096 + t * 256 + s;   // temporal -> spatial row
            }
            float* cp = Cm + (size_t)row * N;
            const float* rp = resid ? resid + (size_t)row * N : nullptr;
            #pragma unroll
            for (int nt = 0; nt < 8; nt++) {
                const int col = bx * 128 + warpN * 64 + nt * 8 + tig * 2;
                float v0 = acc[mt][nt][half * 2 + 0];
                float v1 = acc[mt][nt][half * 2 + 1];
                if (bias) { v0 += bias[col]; v1 += bias[col + 1]; }
                if (rp)   { v0 += rp[col];   v1 += rp[col + 1]; }
                if (GELU) {
                    v0 = 0.5f * v0 * (1.f + erff(v0 * 0.70710678f));
                    v1 = 0.5f * v1 * (1.f + erff(v1 * 0.70710678f));
                }
                if (ROUND) { v0 = to_tf32(v0); v1 = to_tf32(v1); }
                float2 v; v.x = v0; v.y = v1;
                *reinterpret_cast<float2*>(cp + col) = v;
            }
        }
    }
}

// ============================================================
extern "C" void kernel_launch(void* const* d_in, const int* /*in_sizes*/, int /*n_in*/,
                              void* d_out, int /*out_size*/)
{
    const float* x        = (const float*)d_in[0];
    const float* ns_w     = (const float*)d_in[1];
    const float* ns_b     = (const float*)d_in[2];
    const float* nt_w     = (const float*)d_in[3];
    const float* nt_b     = (const float*)d_in[4];
    const float* nm_w     = (const float*)d_in[5];
    const float* nm_b     = (const float*)d_in[6];
    const float* s_qkv    = (const float*)d_in[7];
    const float* s_qkn_w  = (const float*)d_in[8];
    const float* s_qkn_b  = (const float*)d_in[9];
    const float* s_proj_w = (const float*)d_in[10];
    const float* s_proj_b = (const float*)d_in[11];
    const float* t_qkv    = (const float*)d_in[12];
    const float* t_qkn_w  = (const float*)d_in[13];
    const float* t_qkn_b  = (const float*)d_in[14];
    const float* t_proj_w = (const float*)d_in[15];
    const float* t_proj_b = (const float*)d_in[16];
    const float* fc1_w    = (const float*)d_in[17];
    const float* fc1_b    = (const float*)d_in[18];
    const float* fc2_w    = (const float*)d_in[19];
    const float* fc2_b    = (const float*)d_in[20];
    float* out = (float*)d_out;

    float *xbuf, *xln, *qkv, *attn, *hbuf;
    float *wt_sqkv, *wt_sproj, *wt_tqkv, *wt_tproj, *wt_fc1, *wt_fc2;
    cudaGetSymbolAddress((void**)&xbuf, g_xbuf);
    cudaGetSymbolAddress((void**)&xln,  g_xln);
    cudaGetSymbolAddress((void**)&qkv,  g_qkv);
    cudaGetSymbolAddress((void**)&attn, g_attn);
    cudaGetSymbolAddress((void**)&hbuf, g_h);
    cudaGetSymbolAddress((void**)&wt_sqkv,  g_wt_sqkv);
    cudaGetSymbolAddress((void**)&wt_sproj, g_wt_sproj);
    cudaGetSymbolAddress((void**)&wt_tqkv,  g_wt_tqkv);
    cudaGetSymbolAddress((void**)&wt_tproj, g_wt_tproj);
    cudaGetSymbolAddress((void**)&wt_fc1,   g_wt_fc1);
    cudaGetSymbolAddress((void**)&wt_fc2,   g_wt_fc2);

    cudaFuncSetAttribute(attn_kernel, cudaFuncAttributeMaxDynamicSharedMemorySize,
                         256 * 64 * 2 * (int)sizeof(float));
    cudaFuncSetAttribute((const void*)gemm_mma<false, false, false>,
                         cudaFuncAttributeMaxDynamicSharedMemorySize, GEMM_SMEM);
    cudaFuncSetAttribute((const void*)gemm_mma<false, false, true>,
                         cudaFuncAttributeMaxDynamicSharedMemorySize, GEMM_SMEM);
    cudaFuncSetAttribute((const void*)gemm_mma<true,  true,  false>,
                         cudaFuncAttributeMaxDynamicSharedMemorySize, GEMM_SMEM);

    // ---- weight transposes (+ tf32 rounding), once per launch ----
    dim3 tb(32, 8);
    transpose_w<<<dim3(3072/32, 1024/32), tb>>>(s_qkv,    wt_sqkv,  1024, 3072);
    transpose_w<<<dim3(1024/32, 1024/32), tb>>>(s_proj_w, wt_sproj, 1024, 1024);
    transpose_w<<<dim3(3072/32, 1024/32), tb>>>(t_qkv,    wt_tqkv,  1024, 3072);
    transpose_w<<<dim3(1024/32, 1024/32), tb>>>(t_proj_w, wt_tproj, 1024, 1024);
    transpose_w<<<dim3(4096/32, 1024/32), tb>>>(fc1_w,    wt_fc1,   1024, 4096);
    transpose_w<<<dim3(1024/32, 4096/32), tb>>>(fc2_w,    wt_fc2,   4096, 1024);

    const int hl_blocks = (R_ * 2 * H_) / 8;

    // ---- spatial attention block ----
    ln_kernel<false><<<R_, 256>>>(x, xln, ns_w, ns_b);
    gemm_mma<false, false, false><<<dim3(24, 64), 256, GEMM_SMEM>>>(xln, wt_sqkv, qkv, nullptr, nullptr, R_, 3072, 1024);
    headln_kernel<<<hl_blocks, 256>>>(qkv, s_qkn_w, s_qkn_b, SCALE_);
    attn_kernel<<<B_ * T_ * H_, 256, 256 * 64 * 2 * sizeof(float)>>>(qkv, attn);
    gemm_mma<false, false, false><<<dim3(8, 64), 256, GEMM_SMEM>>>(attn, wt_sproj, xbuf, s_proj_b, x, R_, 1024, 1024);

    // ---- temporal attention block (permutes fused into ln + gemm) ----
    ln_kernel<true><<<R_, 256>>>(xbuf, xln, nt_w, nt_b);
    gemm_mma<false, false, false><<<dim3(24, 64), 256, GEMM_SMEM>>>(xln, wt_tqkv, qkv, nullptr, nullptr, R_, 3072, 1024);
    headln_kernel<<<hl_blocks, 256>>>(qkv, t_qkn_w, t_qkn_b, SCALE_);
    attn16_kernel<<<(B_ * S_ * H_) / 16, 256>>>(qkv, attn);
    gemm_mma<false, false, true><<<dim3(8, 64), 256, GEMM_SMEM>>>(attn, wt_tproj, xbuf, t_proj_b, xbuf, R_, 1024, 1024);

    // ---- MLP ----
    ln_kernel<false><<<R_, 256>>>(xbuf, xln, nm_w, nm_b);
    gemm_mma<true,  true,  false><<<dim3(32, 64), 256, GEMM_SMEM>>>(xln, wt_fc1, hbuf, fc1_b, nullptr, R_, 4096, 1024);
    gemm_mma<false, false, false><<<dim3(8, 64), 256, GEMM_SMEM>>>(hbuf, wt_fc2, out, fc2_b, xbuf, R_, 1024, 4096);
}

// round 7
// speedup vs baseline: 2.0928x; 1.1286x over previous
#include <cuda_runtime.h>
#include <cstdint>
#include <math.h>

#define EPSF 1e-5f

constexpr int B_  = 2, T_ = 16, S_ = 256, C_ = 1024, H_ = 16;
constexpr int R_  = B_ * T_ * S_;   // 8192 tokens
constexpr int HID_ = 4 * C_;        // 4096
constexpr float SCALE_ = 8.0f / 64.0f;

// ---- scratch (device globals; no runtime allocation allowed) ----
__device__ float g_xbuf[R_ * C_];
__device__ float g_xln [R_ * C_];
__device__ float g_qkv [R_ * 3 * C_];
__device__ float g_attn[R_ * C_];
__device__ float g_h   [R_ * HID_];
// transposed (tf32-rounded) weights, [N,K] row-major
__device__ float g_wt_sqkv [3 * C_ * C_];
__device__ float g_wt_sproj[C_ * C_];
__device__ float g_wt_tqkv [3 * C_ * C_];
__device__ float g_wt_tproj[C_ * C_];
__device__ float g_wt_fc1  [HID_ * C_];
__device__ float g_wt_fc2  [C_ * HID_];

__device__ __forceinline__ uint32_t smem_u32(const void* p) {
    uint32_t a;
    asm("{ .reg .u64 t; cvta.to.shared.u64 t, %1; cvt.u32.u64 %0, t; }" : "=r"(a) : "l"(p));
    return a;
}
__device__ __forceinline__ float to_tf32(float x) {
    float r;
    asm("cvt.rna.tf32.f32 %0, %1;" : "=f"(r) : "f"(x));
    return r;
}
// e^(s-8) entirely on fma/alu pipes. Valid for s in [-40, 40].
__device__ __forceinline__ float fexp_shift(float s) {
    const float y = fmaf(s, 1.44269504089f, -11.5415603272f);
    const int   i = __float2int_rn(y);
    const float f = y - (float)i;
    float p = fmaf(f, 0.00133335581f, 0.00961812910f);
    p = fmaf(f, p, 0.0555041087f);
    p = fmaf(f, p, 0.240226507f);
    p = fmaf(f, p, 0.693147181f);
    p = fmaf(f, p, 1.0f);
    return __int_as_float(__float_as_int(p) + (i << 23));
}
__device__ __forceinline__ void ldsm4(uint32_t& r0, uint32_t& r1, uint32_t& r2,
                                      uint32_t& r3, uint32_t addr) {
    asm volatile("ldmatrix.sync.aligned.m8n8.x4.b16 {%0,%1,%2,%3}, [%4];"
        : "=r"(r0), "=r"(r1), "=r"(r2), "=r"(r3) : "r"(addr));
}
__device__ __forceinline__ void mma_tf32(float c[4], const uint32_t a[4], const uint32_t b[2]) {
    asm volatile("mma.sync.aligned.m16n8k8.row.col.f32.tf32.tf32.f32 "
        "{%0,%1,%2,%3}, {%4,%5,%6,%7}, {%8,%9}, {%0,%1,%2,%3};"
        : "+f"(c[0]), "+f"(c[1]), "+f"(c[2]), "+f"(c[3])
        : "r"(a[0]), "r"(a[1]), "r"(a[2]), "r"(a[3]), "r"(b[0]), "r"(b[1]));
}

// ============================================================
// Weight transpose + tf32 round: in [K,N] -> out [N,K]
// ============================================================
__global__ void transpose_w(const float* __restrict__ in, float* __restrict__ out,
                            int K, int N)
{
    __shared__ float t[32][33];
    const int n0 = blockIdx.x * 32, k0 = blockIdx.y * 32;
    const int x = threadIdx.x, y = threadIdx.y;
    #pragma unroll
    for (int i = 0; i < 32; i += 8)
        t[y + i][x] = in[(size_t)(k0 + y + i) * N + n0 + x];
    __syncthreads();
    #pragma unroll
    for (int i = 0; i < 32; i += 8)
        out[(size_t)(n0 + y + i) * K + k0 + x] = to_tf32(t[x][y + i]);
}

// ============================================================
// LayerNorm over C=1024. PERM: gather input row through the
// (B,T,S)->(B,S,T) map.
// ============================================================
template<bool PERM>
__global__ void ln_kernel(const float* __restrict__ in, float* __restrict__ out,
                          const float* __restrict__ w, const float* __restrict__ b)
{
    const int row = blockIdx.x, tid = threadIdx.x;
    int in_row = row;
    if (PERM) {
        const int t = row & 15, s = (row >> 4) & 255, bb = row >> 12;
        in_row = bb * 4096 + t * 256 + s;
    }
    const float4 xv = reinterpret_cast<const float4*>(in + (size_t)in_row * 1024)[tid];
    float s  = xv.x + xv.y + xv.z + xv.w;
    float ss = xv.x*xv.x + xv.y*xv.y + xv.z*xv.z + xv.w*xv.w;
    __shared__ float sb[32], ssb[32];
    const int lane = tid & 31, wid = tid >> 5;
    #pragma unroll
    for (int o = 16; o; o >>= 1) {
        s  += __shfl_xor_sync(0xffffffffu, s,  o);
        ss += __shfl_xor_sync(0xffffffffu, ss, o);
    }
    if (lane == 0) { sb[wid] = s; ssb[wid] = ss; }
    __syncthreads();
    if (tid == 0) {
        float ts = 0.f, tss = 0.f;
        #pragma unroll
        for (int i = 0; i < 8; i++) { ts += sb[i]; tss += ssb[i]; }
        float mean = ts * (1.f / 1024.f);
        sb[0]  = mean;
        ssb[0] = rsqrtf(tss * (1.f / 1024.f) - mean * mean + EPSF);
    }
    __syncthreads();
    const float mean = sb[0], rstd = ssb[0];
    const float4 wv = reinterpret_cast<const float4*>(w)[tid];
    const float4 bv = reinterpret_cast<const float4*>(b)[tid];
    float4 o;
    o.x = to_tf32((xv.x - mean) * rstd * wv.x + bv.x);
    o.y = to_tf32((xv.y - mean) * rstd * wv.y + bv.y);
    o.z = to_tf32((xv.z - mean) * rstd * wv.z + bv.z);
    o.w = to_tf32((xv.w - mean) * rstd * wv.w + bv.w);
    reinterpret_cast<float4*>(out + (size_t)row * 1024)[tid] = o;
}

// ============================================================
// Per-head LN (hd=64) on q,k + tf32 rounding of q,k,v.
// One warp per 64-float vector; 48 vectors per token row.
// ============================================================
__global__ void headln_kernel(float* __restrict__ qkv, const float* __restrict__ w,
                              const float* __restrict__ b, float qscale)
{
    const int gw   = (blockIdx.x * blockDim.x + threadIdx.x) >> 5;
    const int lane = threadIdx.x & 31;
    const int r     = gw / 48;
    const int rem   = gw - r * 48;
    const int which = rem >> 4;      // 0 q, 1 k, 2 v
    const int h     = rem & 15;
    float* p = qkv + (size_t)r * 3072 + which * 1024 + h * 64;
    const float v0 = p[lane], v1 = p[lane + 32];
    if (which == 2) {                 // v: round only
        p[lane]      = to_tf32(v0);
        p[lane + 32] = to_tf32(v1);
        return;
    }
    float s = v0 + v1, ss = v0*v0 + v1*v1;
    #pragma unroll
    for (int o = 16; o; o >>= 1) {
        s  += __shfl_xor_sync(0xffffffffu, s,  o);
        ss += __shfl_xor_sync(0xffffffffu, ss, o);
    }
    const float mean = s * (1.f / 64.f);
    const float rstd = rsqrtf(ss * (1.f / 64.f) - mean * mean + EPSF);
    const float sc = which ? 1.f : qscale;
    p[lane]      = to_tf32(((v0 - mean) * rstd * w[lane]      + b[lane])      * sc);
    p[lane + 32] = to_tf32(((v1 - mean) * rstd * w[lane + 32] + b[lane + 32]) * sc);
}

// ============================================================
// Spatial attention on tensor cores. One block per (batch,head).
// Q,K staged swizzled (256B rows); V staged TRANSPOSED (1KB rows).
// Fixed-shift softmax (no running max). 8 key-tiles of 32.
// ============================================================
constexpr int ATTN_SMEM = 3 * 65536;   // Q 64KB | K 64KB | Vt 64KB

__global__ __launch_bounds__(256) void attn_tc(const float* __restrict__ qkv,
                                               float* __restrict__ out)
{
    extern __shared__ float smf[];
    char* smc = (char*)smf;
    const uint32_t Qs = smem_u32(smf);
    const uint32_t Ks = Qs + 65536;
    const uint32_t Vt = Qs + 131072;

    const int tid = threadIdx.x, wid = tid >> 5, lane = tid & 31;
    const int g = lane >> 2, tig = lane & 3;
    const int bh = blockIdx.x, h = bh & 15, batch = bh >> 4;
    const float* base = qkv + (size_t)batch * 256 * 3072;

    // ---- stage Q, K (swizzled) and V (transposed + swizzled) ----
    #pragma unroll
    for (int t = 0; t < 16; t++) {
        const int idx = tid + (t << 8);
        const int r = idx >> 4, c = idx & 15;
        const int dst = r * 256 + ((c ^ (r & 7)) << 4);
        const float4 qv = *(const float4*)(base + (size_t)r * 3072 + h * 64 + c * 4);
        *(float4*)(smc + dst) = qv;
        const float4 kv = *(const float4*)(base + (size_t)r * 3072 + 1024 + h * 64 + c * 4);
        *(float4*)(smc + 65536 + dst) = kv;
        const float4 vv = *(const float4*)(base + (size_t)r * 3072 + 2048 + h * 64 + c * 4);
        const int kc = r >> 2, kb = r & 3;
        const float vvf[4] = {vv.x, vv.y, vv.z, vv.w};
        #pragma unroll
        for (int i = 0; i < 4; i++) {
            const int d = c * 4 + i;
            *(float*)(smc + 131072 + d * 1024 + ((kc ^ (d & 7)) << 4) + kb * 4) = vvf[i];
        }
    }
    __syncthreads();

    // ---- Q fragments (A-side), resident in regs ----
    const int lr = lane & 7;
    const int aRow = wid * 32 + ((lane >> 3) & 1) * 8 + lr;
    const int cbA = lane >> 4;
    uint32_t qf[2][8][4];
    #pragma unroll
    for (int mt = 0; mt < 2; mt++)
        #pragma unroll
        for (int kd = 0; kd < 8; kd++)
            ldsm4(qf[mt][kd][0], qf[mt][kd][1], qf[mt][kd][2], qf[mt][kd][3],
                  Qs + (uint32_t)((aRow + mt * 16) * 256) +
                  (((uint32_t)(2 * kd + cbA) ^ (uint32_t)lr) << 4));

    const int bRow = (lane >> 4) * 8 + lr;
    const int cbB = (lane >> 3) & 1;
    const int srcLo = (lane & 28) + (tig >> 1);
    const bool oddc = tig & 1;

    float o[2][8][4];
    float rs[2][2] = {{0.f, 0.f}, {0.f, 0.f}};
    #pragma unroll
    for (int mt = 0; mt < 2; mt++)
        #pragma unroll
        for (int no = 0; no < 8; no++)
            #pragma unroll
            for (int i = 0; i < 4; i++) o[mt][no][i] = 0.f;

    for (int tile = 0; tile < 8; tile++) {
        // ---- S = Q @ K^T (32 keys) ----
        float s[2][4][4];
        #pragma unroll
        for (int mt = 0; mt < 2; mt++)
            #pragma unroll
            for (int nt = 0; nt < 4; nt++)
                #pragma unroll
                for (int i = 0; i < 4; i++) s[mt][nt][i] = 0.f;
        #pragma unroll
        for (int kd = 0; kd < 8; kd++) {
            uint32_t kb_[4][2];
            #pragma unroll
            for (int ntp = 0; ntp < 2; ntp++)
                ldsm4(kb_[2*ntp][0], kb_[2*ntp][1], kb_[2*ntp+1][0], kb_[2*ntp+1][1],
                      Ks + (uint32_t)((tile * 32 + bRow + ntp * 16) * 256) +
                      (((uint32_t)(2 * kd + cbB) ^ (uint32_t)lr) << 4));
            #pragma unroll
            for (int mt = 0; mt < 2; mt++)
                #pragma unroll
                for (int nt = 0; nt < 4; nt++)
                    mma_tf32(s[mt][nt], qf[mt][kd], kb_[nt]);
        }
        // ---- softmax weights (fixed shift), row-sum partials ----
        #pragma unroll
        for (int mt = 0; mt < 2; mt++)
            #pragma unroll
            for (int nt = 0; nt < 4; nt++)
                #pragma unroll
                for (int i = 0; i < 4; i++) {
                    const float e = fexp_shift(s[mt][nt][i]);
                    rs[mt][i >> 1] += e;
                    s[mt][nt][i] = to_tf32(e);
                }
        // ---- O += P @ V ----
        #pragma unroll
        for (int ka = 0; ka < 4; ka++) {
            uint32_t vb[8][2];
            #pragma unroll
            for (int ntp = 0; ntp < 4; ntp++)
                ldsm4(vb[2*ntp][0], vb[2*ntp][1], vb[2*ntp+1][0], vb[2*ntp+1][1],
                      Vt + (uint32_t)((bRow + ntp * 16) * 1024) +
                      (((uint32_t)(tile * 8 + 2 * ka + cbB) ^ (uint32_t)lr) << 4));
            uint32_t pa[2][4];
            #pragma unroll
            for (int mt = 0; mt < 2; mt++) {
                const float e0 = __shfl_sync(0xffffffffu, s[mt][ka][0], srcLo);
                const float e1 = __shfl_sync(0xffffffffu, s[mt][ka][1], srcLo);
                const float e2 = __shfl_sync(0xffffffffu, s[mt][ka][2], srcLo);
                const float e3 = __shfl_sync(0xffffffffu, s[mt][ka][3], srcLo);
                const float f0 = __shfl_sync(0xffffffffu, s[mt][ka][0], srcLo + 2);
                const float f1 = __shfl_sync(0xffffffffu, s[mt][ka][1], srcLo + 2);
                const float f2 = __shfl_sync(0xffffffffu, s[mt][ka][2], srcLo + 2);
                const float f3 = __shfl_sync(0xffffffffu, s[mt][ka][3], srcLo + 2);
                pa[mt][0] = __float_as_uint(oddc ? e1 : e0);
                pa[mt][1] = __float_as_uint(oddc ? e3 : e2);
                pa[mt][2] = __float_as_uint(oddc ? f1 : f0);
                pa[mt][3] = __float_as_uint(oddc ? f3 : f2);
            }
            #pragma unroll
            for (int mt = 0; mt < 2; mt++)
                #pragma unroll
                for (int no = 0; no < 8; no++)
                    mma_tf32(o[mt][no], pa[mt], vb[no]);
        }
    }

    // ---- normalize & write ----
    #pragma unroll
    for (int mt = 0; mt < 2; mt++)
        #pragma unroll
        for (int i = 0; i < 2; i++) {
            float v = rs[mt][i];
            v += __shfl_xor_sync(0xffffffffu, v, 1);
            v += __shfl_xor_sync(0xffffffffu, v, 2);
            rs[mt][i] = 1.f / v;
        }
    #pragma unroll
    for (int mt = 0; mt < 2; mt++) {
        const int r0 = wid * 32 + mt * 16 + g;
        float* p0 = out + ((size_t)batch * 256 + r0) * 1024 + h * 64;
        float* p1 = p0 + 8 * 1024;
        #pragma unroll
        for (int no = 0; no < 8; no++) {
            float2 w0, w1;
            w0.x = to_tf32(o[mt][no][0] * rs[mt][0]);
            w0.y = to_tf32(o[mt][no][1] * rs[mt][0]);
            w1.x = to_tf32(o[mt][no][2] * rs[mt][1]);
            w1.y = to_tf32(o[mt][no][3] * rs[mt][1]);
            *(float2*)(p0 + no * 8 + tig * 2) = w0;
            *(float2*)(p1 + no * 8 + tig * 2) = w1;
        }
    }
}

// ============================================================
// Temporal attention (N=16): 256-thread blocks, 16 groups/block
// ============================================================
__global__ void attn16_kernel(const float* __restrict__ qkv, float* __restrict__ out)
{
    constexpr int N = 16;
    const int tid = threadIdx.x;
    const int bh = blockIdx.x * 16 + (tid >> 4);
    const int h = bh & 15;
    const int batch = bh >> 4;
    const int row = tid & 15;
    const float* base = qkv + (size_t)batch * N * 3072;

    float4 q[16];
    const float4* qp = reinterpret_cast<const float4*>(base + (size_t)row * 3072 + h * 64);
    #pragma unroll
    for (int d = 0; d < 16; d++) q[d] = qp[d];

    float4 acc[16];
    #pragma unroll
    for (int d = 0; d < 16; d++) acc[d] = make_float4(0.f, 0.f, 0.f, 0.f);
    float sum = 0.f;
    #pragma unroll
    for (int j = 0; j < N; j++) {
        const float4* kr = reinterpret_cast<const float4*>(base + (size_t)j * 3072 + 1024 + h * 64);
        float s = 0.f;
        #pragma unroll
        for (int d = 0; d < 16; d++) {
            const float4 kv = kr[d];
            s += q[d].x*kv.x + q[d].y*kv.y + q[d].z*kv.z + q[d].w*kv.w;
        }
        const float e = fexp_shift(s);
        sum += e;
        const float4* vr = reinterpret_cast<const float4*>(base + (size_t)j * 3072 + 2048 + h * 64);
        #pragma unroll
        for (int d = 0; d < 16; d++) {
            const float4 vv = vr[d];
            acc[d].x += e * vv.x; acc[d].y += e * vv.y;
            acc[d].z += e * vv.z; acc[d].w += e * vv.w;
        }
    }
    const float inv = 1.f / sum;
    float4* op = reinterpret_cast<float4*>(out + ((size_t)batch * N + row) * 1024 + h * 64);
    #pragma unroll
    for (int d = 0; d < 16; d++)
        op[d] = make_float4(to_tf32(acc[d].x * inv), to_tf32(acc[d].y * inv),
                            to_tf32(acc[d].z * inv), to_tf32(acc[d].w * inv));
}

// ============================================================
// Tensor-core GEMM via mma.sync (tf32) + ldmatrix (unchanged R5)
// ============================================================
constexpr int STG_B    = 32768;
constexpr int GEMM_SMEM = 2 * STG_B;

template<bool GELU, bool ROUND, bool PERMROW>
__global__ __launch_bounds__(256, 2) void gemm_mma(
    const float* __restrict__ A, const float* __restrict__ Bt,
    float* __restrict__ Cm, const float* __restrict__ bias,
    const float* __restrict__ resid, int M, int N, int K)
{
    extern __shared__ float sm[];
    const uint32_t stg = smem_u32(sm);

    const int tid = threadIdx.x;
    const int wid = tid >> 5, lane = tid & 31;
    const int g = lane >> 2, tig = lane & 3;
    const int warpM = wid & 3, warpN = wid >> 2;
    const int bx = blockIdx.x, by = blockIdx.y;
    const int NKB = K >> 5;

    uint32_t a_s[4], b_s[4];
    const float *a_g[4], *b_g[4];
    #pragma unroll
    for (int t = 0; t < 4; t++) {
        const int idx = tid + (t << 8);
        const int r = idx >> 3, c = idx & 7;
        const uint32_t sw = (uint32_t)(r * 128 + ((c ^ (r & 7)) << 4));
        a_s[t] = sw;            b_s[t] = sw + 16384;
        a_g[t] = A  + (size_t)(by * 128 + r) * K + c * 4;
        b_g[t] = Bt + (size_t)(bx * 128 + r) * K + c * 4;
    }

    auto load_stage = [&](int s, int kb) {
        const uint32_t sb = stg + s * STG_B;
        const int ko = kb << 5;
        #pragma unroll
        for (int t = 0; t < 4; t++)
            asm volatile("cp.async.cg.shared.global [%0], [%1], 16;" ::
                "r"(sb + a_s[t]), "l"(a_g[t] + ko) : "memory");
        #pragma unroll
        for (int t = 0; t < 4; t++)
            asm volatile("cp.async.cg.shared.global [%0], [%1], 16;" ::
                "r"(sb + b_s[t]), "l"(b_g[t] + ko) : "memory");
    };

    const int lr = lane & 7;
    const int aRow = warpM * 32 + ((lane >> 3) & 1) * 8 + lr;
    const int cbA  = lane >> 4;
    const uint32_t aRx = (uint32_t)(aRow * 128);
    const uint32_t a7  = (uint32_t)(aRow & 7);
    const int bRow = warpN * 64 + (lane >> 4) * 8 + lr;
    const int cbB  = (lane >> 3) & 1;
    const uint32_t bRx = (uint32_t)(bRow * 128);
    const uint32_t b7  = (uint32_t)(bRow & 7);

    float acc[2][8][4];
    #pragma unroll
    for (int mt = 0; mt < 2; mt++)
        #pragma unroll
        for (int nt = 0; nt < 8; nt++)
            #pragma unroll
            for (int i = 0; i < 4; i++) acc[mt][nt][i] = 0.f;

    load_stage(0, 0);
    asm volatile("cp.async.commit_group;" ::: "memory");

    for (int kb = 0; kb < NKB; kb++) {
        if (kb + 1 < NKB) {
            load_stage((kb + 1) & 1, kb + 1);
            asm volatile("cp.async.commit_group;" ::: "memory");
            asm volatile("cp.async.wait_group 1;" ::: "memory");
        } else {
            asm volatile("cp.async.wait_group 0;" ::: "memory");
        }
        __syncthreads();

        const uint32_t sA = stg + (kb & 1) * STG_B;
        const uint32_t sB = sA + 16384;
        #pragma unroll
        for (int ks = 0; ks < 4; ks++) {
            uint32_t a[2][4], b[8][2];
            const uint32_t swA = ((uint32_t)(2 * ks + cbA) ^ a7) << 4;
            #pragma unroll
            for (int mt = 0; mt < 2; mt++)
                ldsm4(a[mt][0], a[mt][1], a[mt][2], a[mt][3],
                      sA + aRx + (uint32_t)(mt * 16 * 128) + swA);
            const uint32_t swB = ((uint32_t)(2 * ks + cbB) ^ b7) << 4;
            #pragma unroll
            for (int ntp = 0; ntp < 4; ntp++)
                ldsm4(b[2 * ntp][0], b[2 * ntp][1], b[2 * ntp + 1][0], b[2 * ntp + 1][1],
                      sB + bRx + (uint32_t)(ntp * 16 * 128) + swB);
            #pragma unroll
            for (int mt = 0; mt < 2; mt++)
                #pragma unroll
                for (int nt = 0; nt < 8; nt++)
                    mma_tf32(acc[mt][nt], a[mt], b[nt]);
        }
        __syncthreads();
    }

    #pragma unroll
    for (int mt = 0; mt < 2; mt++) {
        #pragma unroll
        for (int half = 0; half < 2; half++) {
            int row = by * 128 + warpM * 32 + mt * 16 + g + half * 8;
            if (PERMROW) {
                const int t = row & 15, s = (row >> 4) & 255, bb = row >> 12;
                row = bb * 4096 + t * 256 + s;
            }
            float* cp = Cm + (size_t)row * N;
            const float* rp = resid ? resid + (size_t)row * N : nullptr;
            #pragma unroll
            for (int nt = 0; nt < 8; nt++) {
                const int col = bx * 128 + warpN * 64 + nt * 8 + tig * 2;
                float v0 = acc[mt][nt][half * 2 + 0];
                float v1 = acc[mt][nt][half * 2 + 1];
                if (bias) { v0 += bias[col]; v1 += bias[col + 1]; }
                if (rp)   { v0 += rp[col];   v1 += rp[col + 1]; }
                if (GELU) {
                    v0 = 0.5f * v0 * (1.f + erff(v0 * 0.70710678f));
                    v1 = 0.5f * v1 * (1.f + erff(v1 * 0.70710678f));
                }
                if (ROUND) { v0 = to_tf32(v0); v1 = to_tf32(v1); }
                float2 v; v.x = v0; v.y = v1;
                *reinterpret_cast<float2*>(cp + col) = v;
            }
        }
    }
}

// ============================================================
extern "C" void kernel_launch(void* const* d_in, const int* /*in_sizes*/, int /*n_in*/,
                              void* d_out, int /*out_size*/)
{
    const float* x        = (const float*)d_in[0];
    const float* ns_w     = (const float*)d_in[1];
    const float* ns_b     = (const float*)d_in[2];
    const float* nt_w     = (const float*)d_in[3];
    const float* nt_b     = (const float*)d_in[4];
    const float* nm_w     = (const float*)d_in[5];
    const float* nm_b     = (const float*)d_in[6];
    const float* s_qkv    = (const float*)d_in[7];
    const float* s_qkn_w  = (const float*)d_in[8];
    const float* s_qkn_b  = (const float*)d_in[9];
    const float* s_proj_w = (const float*)d_in[10];
    const float* s_proj_b = (const float*)d_in[11];
    const float* t_qkv    = (const float*)d_in[12];
    const float* t_qkn_w  = (const float*)d_in[13];
    const float* t_qkn_b  = (const float*)d_in[14];
    const float* t_proj_w = (const float*)d_in[15];
    const float* t_proj_b = (const float*)d_in[16];
    const float* fc1_w    = (const float*)d_in[17];
    const float* fc1_b    = (const float*)d_in[18];
    const float* fc2_w    = (const float*)d_in[19];
    const float* fc2_b    = (const float*)d_in[20];
    float* out = (float*)d_out;

    float *xbuf, *xln, *qkv, *attn, *hbuf;
    float *wt_sqkv, *wt_sproj, *wt_tqkv, *wt_tproj, *wt_fc1, *wt_fc2;
    cudaGetSymbolAddress((void**)&xbuf, g_xbuf);
    cudaGetSymbolAddress((void**)&xln,  g_xln);
    cudaGetSymbolAddress((void**)&qkv,  g_qkv);
    cudaGetSymbolAddress((void**)&attn, g_attn);
    cudaGetSymbolAddress((void**)&hbuf, g_h);
    cudaGetSymbolAddress((void**)&wt_sqkv,  g_wt_sqkv);
    cudaGetSymbolAddress((void**)&wt_sproj, g_wt_sproj);
    cudaGetSymbolAddress((void**)&wt_tqkv,  g_wt_tqkv);
    cudaGetSymbolAddress((void**)&wt_tproj, g_wt_tproj);
    cudaGetSymbolAddress((void**)&wt_fc1,   g_wt_fc1);
    cudaGetSymbolAddress((void**)&wt_fc2,   g_wt_fc2);

    cudaFuncSetAttribute(attn_tc, cudaFuncAttributeMaxDynamicSharedMemorySize, ATTN_SMEM);
    cudaFuncSetAttribute((const void*)gemm_mma<false, false, false>,
                         cudaFuncAttributeMaxDynamicSharedMemorySize, GEMM_SMEM);
    cudaFuncSetAttribute((const void*)gemm_mma<false, false, true>,
                         cudaFuncAttributeMaxDynamicSharedMemorySize, GEMM_SMEM);
    cudaFuncSetAttribute((const void*)gemm_mma<true,  true,  false>,
                         cudaFuncAttributeMaxDynamicSharedMemorySize, GEMM_SMEM);

    // ---- weight transposes (+ tf32 rounding), once per launch ----
    dim3 tb(32, 8);
    transpose_w<<<dim3(3072/32, 1024/32), tb>>>(s_qkv,    wt_sqkv,  1024, 3072);
    transpose_w<<<dim3(1024/32, 1024/32), tb>>>(s_proj_w, wt_sproj, 1024, 1024);
    transpose_w<<<dim3(3072/32, 1024/32), tb>>>(t_qkv,    wt_tqkv,  1024, 3072);
    transpose_w<<<dim3(1024/32, 1024/32), tb>>>(t_proj_w, wt_tproj, 1024, 1024);
    transpose_w<<<dim3(4096/32, 1024/32), tb>>>(fc1_w,    wt_fc1,   1024, 4096);
    transpose_w<<<dim3(1024/32, 4096/32), tb>>>(fc2_w,    wt_fc2,   4096, 1024);

    const int hl_blocks = (R_ * 3 * H_) / 8;   // 48 vectors/row, 8 warps/block

    // ---- spatial attention block ----
    ln_kernel<false><<<R_, 256>>>(x, xln, ns_w, ns_b);
    gemm_mma<false, false, false><<<dim3(24, 64), 256, GEMM_SMEM>>>(xln, wt_sqkv, qkv, nullptr, nullptr, R_, 3072, 1024);
    headln_kernel<<<hl_blocks, 256>>>(qkv, s_qkn_w, s_qkn_b, SCALE_);
    attn_tc<<<B_ * T_ * H_, 256, ATTN_SMEM>>>(qkv, attn);
    gemm_mma<false, false, false><<<dim3(8, 64), 256, GEMM_SMEM>>>(attn, wt_sproj, xbuf, s_proj_b, x, R_, 1024, 1024);

    // ---- temporal attention block (permutes fused into ln + gemm) ----
    ln_kernel<true><<<R_, 256>>>(xbuf, xln, nt_w, nt_b);
    gemm_mma<false, false, false><<<dim3(24, 64), 256, GEMM_SMEM>>>(xln, wt_tqkv, qkv, nullptr, nullptr, R_, 3072, 1024);
    headln_kernel<<<hl_blocks, 256>>>(qkv, t_qkn_w, t_qkn_b, SCALE_);
    attn16_kernel<<<(B_ * S_ * H_) / 16, 256>>>(qkv, attn);
    gemm_mma<false, false, true><<<dim3(8, 64), 256, GEMM_SMEM>>>(attn, wt_tproj, xbuf, t_proj_b, xbuf, R_, 1024, 1024);

    // ---- MLP ----
    ln_kernel<false><<<R_, 256>>>(xbuf, xln, nm_w, nm_b);
    gemm_mma<true,  true,  false><<<dim3(32, 64), 256, GEMM_SMEM>>>(xln, wt_fc1, hbuf, fc1_b, nullptr, R_, 4096, 1024);
    gemm_mma<false, false, false><<<dim3(8, 64), 256, GEMM_SMEM>>>(hbuf, wt_fc2, out, fc2_b, xbuf, R_, 1024, 4096);
}

// round 8
// speedup vs baseline: 3.2820x; 1.5682x over previous
#include <cuda_runtime.h>
#include <cuda_fp16.h>
#include <cstdint>
#include <math.h>

#define EPSF 1e-5f

constexpr int B_  = 2, T_ = 16, S_ = 256, C_ = 1024, H_ = 16;
constexpr int R_  = B_ * T_ * S_;   // 8192 tokens
constexpr int HID_ = 4 * C_;        // 4096
constexpr float SCALE_ = 8.0f / 64.0f;

// ---- scratch (device globals; no runtime allocation allowed) ----
__device__ float  g_xbuf[R_ * C_];
__device__ __half g_xln [R_ * C_];
__device__ float  g_qkv [R_ * 3 * C_];
__device__ __half g_attn[R_ * C_];
__device__ __half g_h   [R_ * HID_];
// transposed (fp16) weights, [N,K] row-major
__device__ __half g_wt_sqkv [3 * C_ * C_];
__device__ __half g_wt_sproj[C_ * C_];
__device__ __half g_wt_tqkv [3 * C_ * C_];
__device__ __half g_wt_tproj[C_ * C_];
__device__ __half g_wt_fc1  [HID_ * C_];
__device__ __half g_wt_fc2  [C_ * HID_];

__device__ __forceinline__ uint32_t smem_u32(const void* p) {
    uint32_t a;
    asm("{ .reg .u64 t; cvta.to.shared.u64 t, %1; cvt.u32.u64 %0, t; }" : "=r"(a) : "l"(p));
    return a;
}
__device__ __forceinline__ float to_tf32(float x) {
    float r;
    asm("cvt.rna.tf32.f32 %0, %1;" : "=f"(r) : "f"(x));
    return r;
}
// e^(s-8) entirely on fma/alu pipes. Valid for s in [-40, 40].
__device__ __forceinline__ float fexp_shift(float s) {
    const float y = fmaf(s, 1.44269504089f, -11.5415603272f);
    const int   i = __float2int_rn(y);
    const float f = y - (float)i;
    float p = fmaf(f, 0.00133335581f, 0.00961812910f);
    p = fmaf(f, p, 0.0555041087f);
    p = fmaf(f, p, 0.240226507f);
    p = fmaf(f, p, 0.693147181f);
    p = fmaf(f, p, 1.0f);
    return __int_as_float(__float_as_int(p) + (i << 23));
}
__device__ __forceinline__ void ldsm4(uint32_t& r0, uint32_t& r1, uint32_t& r2,
                                      uint32_t& r3, uint32_t addr) {
    asm volatile("ldmatrix.sync.aligned.m8n8.x4.b16 {%0,%1,%2,%3}, [%4];"
        : "=r"(r0), "=r"(r1), "=r"(r2), "=r"(r3) : "r"(addr));
}
__device__ __forceinline__ void mma_tf32(float c[4], const uint32_t a[4], const uint32_t b[2]) {
    asm volatile("mma.sync.aligned.m16n8k8.row.col.f32.tf32.tf32.f32 "
        "{%0,%1,%2,%3}, {%4,%5,%6,%7}, {%8,%9}, {%0,%1,%2,%3};"
        : "+f"(c[0]), "+f"(c[1]), "+f"(c[2]), "+f"(c[3])
        : "r"(a[0]), "r"(a[1]), "r"(a[2]), "r"(a[3]), "r"(b[0]), "r"(b[1]));
}
__device__ __forceinline__ void mma_f16(float c[4], const uint32_t a[4], const uint32_t b[2]) {
    asm volatile("mma.sync.aligned.m16n8k16.row.col.f32.f16.f16.f32 "
        "{%0,%1,%2,%3}, {%4,%5,%6,%7}, {%8,%9}, {%0,%1,%2,%3};"
        : "+f"(c[0]), "+f"(c[1]), "+f"(c[2]), "+f"(c[3])
        : "r"(a[0]), "r"(a[1]), "r"(a[2]), "r"(a[3]), "r"(b[0]), "r"(b[1]));
}

// ============================================================
// Weight transpose + fp16 round: in [K,N] float -> out [N,K] half
// ============================================================
__global__ void transpose_w(const float* __restrict__ in, __half* __restrict__ out,
                            int K, int N)
{
    __shared__ float t[32][33];
    const int n0 = blockIdx.x * 32, k0 = blockIdx.y * 32;
    const int x = threadIdx.x, y = threadIdx.y;
    #pragma unroll
    for (int i = 0; i < 32; i += 8)
        t[y + i][x] = in[(size_t)(k0 + y + i) * N + n0 + x];
    __syncthreads();
    #pragma unroll
    for (int i = 0; i < 32; i += 8)
        out[(size_t)(n0 + y + i) * K + k0 + x] = __float2half_rn(t[x][y + i]);
}

// ============================================================
// LayerNorm over C=1024 -> fp16 (feeds GEMM A). PERM gathers
// through the (B,T,S)->(B,S,T) map.
// ============================================================
template<bool PERM>
__global__ void ln_kernel(const float* __restrict__ in, __half* __restrict__ out,
                          const float* __restrict__ w, const float* __restrict__ b)
{
    const int row = blockIdx.x, tid = threadIdx.x;
    int in_row = row;
    if (PERM) {
        const int t = row & 15, s = (row >> 4) & 255, bb = row >> 12;
        in_row = bb * 4096 + t * 256 + s;
    }
    const float4 xv = reinterpret_cast<const float4*>(in + (size_t)in_row * 1024)[tid];
    float s  = xv.x + xv.y + xv.z + xv.w;
    float ss = xv.x*xv.x + xv.y*xv.y + xv.z*xv.z + xv.w*xv.w;
    __shared__ float sb[32], ssb[32];
    const int lane = tid & 31, wid = tid >> 5;
    #pragma unroll
    for (int o = 16; o; o >>= 1) {
        s  += __shfl_xor_sync(0xffffffffu, s,  o);
        ss += __shfl_xor_sync(0xffffffffu, ss, o);
    }
    if (lane == 0) { sb[wid] = s; ssb[wid] = ss; }
    __syncthreads();
    if (tid == 0) {
        float ts = 0.f, tss = 0.f;
        #pragma unroll
        for (int i = 0; i < 8; i++) { ts += sb[i]; tss += ssb[i]; }
        float mean = ts * (1.f / 1024.f);
        sb[0]  = mean;
        ssb[0] = rsqrtf(tss * (1.f / 1024.f) - mean * mean + EPSF);
    }
    __syncthreads();
    const float mean = sb[0], rstd = ssb[0];
    const float4 wv = reinterpret_cast<const float4*>(w)[tid];
    const float4 bv = reinterpret_cast<const float4*>(b)[tid];
    __half2 o0 = __floats2half2_rn((xv.x - mean) * rstd * wv.x + bv.x,
                                   (xv.y - mean) * rstd * wv.y + bv.y);
    __half2 o1 = __floats2half2_rn((xv.z - mean) * rstd * wv.z + bv.z,
                                   (xv.w - mean) * rstd * wv.w + bv.w);
    uint2 pk;
    pk.x = *(uint32_t*)&o0; pk.y = *(uint32_t*)&o1;
    reinterpret_cast<uint2*>(out + (size_t)row * 1024)[tid] = pk;
}

// ============================================================
// Per-head LN (hd=64) on q,k + tf32 rounding of q,k,v (float qkv)
// ============================================================
__global__ void headln_kernel(float* __restrict__ qkv, const float* __restrict__ w,
                              const float* __restrict__ b, float qscale)
{
    const int gw   = (blockIdx.x * blockDim.x + threadIdx.x) >> 5;
    const int lane = threadIdx.x & 31;
    const int r     = gw / 48;
    const int rem   = gw - r * 48;
    const int which = rem >> 4;      // 0 q, 1 k, 2 v
    const int h     = rem & 15;
    float* p = qkv + (size_t)r * 3072 + which * 1024 + h * 64;
    const float v0 = p[lane], v1 = p[lane + 32];
    if (which == 2) {
        p[lane]      = to_tf32(v0);
        p[lane + 32] = to_tf32(v1);
        return;
    }
    float s = v0 + v1, ss = v0*v0 + v1*v1;
    #pragma unroll
    for (int o = 16; o; o >>= 1) {
        s  += __shfl_xor_sync(0xffffffffu, s,  o);
        ss += __shfl_xor_sync(0xffffffffu, ss, o);
    }
    const float mean = s * (1.f / 64.f);
    const float rstd = rsqrtf(ss * (1.f / 64.f) - mean * mean + EPSF);
    const float sc = which ? 1.f : qscale;
    p[lane]      = to_tf32(((v0 - mean) * rstd * w[lane]      + b[lane])      * sc);
    p[lane + 32] = to_tf32(((v1 - mean) * rstd * w[lane + 32] + b[lane + 32]) * sc);
}

// ============================================================
// Spatial attention on tensor cores (tf32 internals, fp16 out).
// ============================================================
constexpr int ATTN_SMEM = 3 * 65536;

__global__ __launch_bounds__(256) void attn_tc(const float* __restrict__ qkv,
                                               __half* __restrict__ out)
{
    extern __shared__ float smf[];
    char* smc = (char*)smf;
    const uint32_t Qs = smem_u32(smf);
    const uint32_t Ks = Qs + 65536;
    const uint32_t Vt = Qs + 131072;

    const int tid = threadIdx.x, wid = tid >> 5, lane = tid & 31;
    const int g = lane >> 2, tig = lane & 3;
    const int bh = blockIdx.x, h = bh & 15, batch = bh >> 4;
    const float* base = qkv + (size_t)batch * 256 * 3072;

    #pragma unroll
    for (int t = 0; t < 16; t++) {
        const int idx = tid + (t << 8);
        const int r = idx >> 4, c = idx & 15;
        const int dst = r * 256 + ((c ^ (r & 7)) << 4);
        const float4 qv = *(const float4*)(base + (size_t)r * 3072 + h * 64 + c * 4);
        *(float4*)(smc + dst) = qv;
        const float4 kv = *(const float4*)(base + (size_t)r * 3072 + 1024 + h * 64 + c * 4);
        *(float4*)(smc + 65536 + dst) = kv;
        const float4 vv = *(const float4*)(base + (size_t)r * 3072 + 2048 + h * 64 + c * 4);
        const int kc = r >> 2, kb = r & 3;
        const float vvf[4] = {vv.x, vv.y, vv.z, vv.w};
        #pragma unroll
        for (int i = 0; i < 4; i++) {
            const int d = c * 4 + i;
            *(float*)(smc + 131072 + d * 1024 + ((kc ^ (d & 7)) << 4) + kb * 4) = vvf[i];
        }
    }
    __syncthreads();

    const int lr = lane & 7;
    const int aRow = wid * 32 + ((lane >> 3) & 1) * 8 + lr;
    const int cbA = lane >> 4;
    uint32_t qf[2][8][4];
    #pragma unroll
    for (int mt = 0; mt < 2; mt++)
        #pragma unroll
        for (int kd = 0; kd < 8; kd++)
            ldsm4(qf[mt][kd][0], qf[mt][kd][1], qf[mt][kd][2], qf[mt][kd][3],
                  Qs + (uint32_t)((aRow + mt * 16) * 256) +
                  (((uint32_t)(2 * kd + cbA) ^ (uint32_t)lr) << 4));

    const int bRow = (lane >> 4) * 8 + lr;
    const int cbB = (lane >> 3) & 1;
    const int srcLo = (lane & 28) + (tig >> 1);
    const bool oddc = tig & 1;

    float o[2][8][4];
    float rs[2][2] = {{0.f, 0.f}, {0.f, 0.f}};
    #pragma unroll
    for (int mt = 0; mt < 2; mt++)
        #pragma unroll
        for (int no = 0; no < 8; no++)
            #pragma unroll
            for (int i = 0; i < 4; i++) o[mt][no][i] = 0.f;

    for (int tile = 0; tile < 8; tile++) {
        float s[2][4][4];
        #pragma unroll
        for (int mt = 0; mt < 2; mt++)
            #pragma unroll
            for (int nt = 0; nt < 4; nt++)
                #pragma unroll
                for (int i = 0; i < 4; i++) s[mt][nt][i] = 0.f;
        #pragma unroll
        for (int kd = 0; kd < 8; kd++) {
            uint32_t kb_[4][2];
            #pragma unroll
            for (int ntp = 0; ntp < 2; ntp++)
                ldsm4(kb_[2*ntp][0], kb_[2*ntp][1], kb_[2*ntp+1][0], kb_[2*ntp+1][1],
                      Ks + (uint32_t)((tile * 32 + bRow + ntp * 16) * 256) +
                      (((uint32_t)(2 * kd + cbB) ^ (uint32_t)lr) << 4));
            #pragma unroll
            for (int mt = 0; mt < 2; mt++)
                #pragma unroll
                for (int nt = 0; nt < 4; nt++)
                    mma_tf32(s[mt][nt], qf[mt][kd], kb_[nt]);
        }
        #pragma unroll
        for (int mt = 0; mt < 2; mt++)
            #pragma unroll
            for (int nt = 0; nt < 4; nt++)
                #pragma unroll
                for (int i = 0; i < 4; i++) {
                    const float e = fexp_shift(s[mt][nt][i]);
                    rs[mt][i >> 1] += e;
                    s[mt][nt][i] = to_tf32(e);
                }
        #pragma unroll
        for (int ka = 0; ka < 4; ka++) {
            uint32_t vb[8][2];
            #pragma unroll
            for (int ntp = 0; ntp < 4; ntp++)
                ldsm4(vb[2*ntp][0], vb[2*ntp][1], vb[2*ntp+1][0], vb[2*ntp+1][1],
                      Vt + (uint32_t)((bRow + ntp * 16) * 1024) +
                      (((uint32_t)(tile * 8 + 2 * ka + cbB) ^ (uint32_t)lr) << 4));
            uint32_t pa[2][4];
            #pragma unroll
            for (int mt = 0; mt < 2; mt++) {
                const float e0 = __shfl_sync(0xffffffffu, s[mt][ka][0], srcLo);
                const float e1 = __shfl_sync(0xffffffffu, s[mt][ka][1], srcLo);
                const float e2 = __shfl_sync(0xffffffffu, s[mt][ka][2], srcLo);
                const float e3 = __shfl_sync(0xffffffffu, s[mt][ka][3], srcLo);
                const float f0 = __shfl_sync(0xffffffffu, s[mt][ka][0], srcLo + 2);
                const float f1 = __shfl_sync(0xffffffffu, s[mt][ka][1], srcLo + 2);
                const float f2 = __shfl_sync(0xffffffffu, s[mt][ka][2], srcLo + 2);
                const float f3 = __shfl_sync(0xffffffffu, s[mt][ka][3], srcLo + 2);
                pa[mt][0] = __float_as_uint(oddc ? e1 : e0);
                pa[mt][1] = __float_as_uint(oddc ? e3 : e2);
                pa[mt][2] = __float_as_uint(oddc ? f1 : f0);
                pa[mt][3] = __float_as_uint(oddc ? f3 : f2);
            }
            #pragma unroll
            for (int mt = 0; mt < 2; mt++)
                #pragma unroll
                for (int no = 0; no < 8; no++)
                    mma_tf32(o[mt][no], pa[mt], vb[no]);
        }
    }

    #pragma unroll
    for (int mt = 0; mt < 2; mt++)
        #pragma unroll
        for (int i = 0; i < 2; i++) {
            float v = rs[mt][i];
            v += __shfl_xor_sync(0xffffffffu, v, 1);
            v += __shfl_xor_sync(0xffffffffu, v, 2);
            rs[mt][i] = 1.f / v;
        }
    #pragma unroll
    for (int mt = 0; mt < 2; mt++) {
        const int r0 = wid * 32 + mt * 16 + g;
        __half* p0 = out + ((size_t)batch * 256 + r0) * 1024 + h * 64;
        __half* p1 = p0 + 8 * 1024;
        #pragma unroll
        for (int no = 0; no < 8; no++) {
            __half2 w0 = __floats2half2_rn(o[mt][no][0] * rs[mt][0], o[mt][no][1] * rs[mt][0]);
            __half2 w1 = __floats2half2_rn(o[mt][no][2] * rs[mt][1], o[mt][no][3] * rs[mt][1]);
            *(__half2*)(p0 + no * 8 + tig * 2) = w0;
            *(__half2*)(p1 + no * 8 + tig * 2) = w1;
        }
    }
}

// ============================================================
// Temporal attention (N=16): fp16 output
// ============================================================
__global__ void attn16_kernel(const float* __restrict__ qkv, __half* __restrict__ out)
{
    constexpr int N = 16;
    const int tid = threadIdx.x;
    const int bh = blockIdx.x * 16 + (tid >> 4);
    const int h = bh & 15;
    const int batch = bh >> 4;
    const int row = tid & 15;
    const float* base = qkv + (size_t)batch * N * 3072;

    float4 q[16];
    const float4* qp = reinterpret_cast<const float4*>(base + (size_t)row * 3072 + h * 64);
    #pragma unroll
    for (int d = 0; d < 16; d++) q[d] = qp[d];

    float4 acc[16];
    #pragma unroll
    for (int d = 0; d < 16; d++) acc[d] = make_float4(0.f, 0.f, 0.f, 0.f);
    float sum = 0.f;
    #pragma unroll
    for (int j = 0; j < N; j++) {
        const float4* kr = reinterpret_cast<const float4*>(base + (size_t)j * 3072 + 1024 + h * 64);
        float s = 0.f;
        #pragma unroll
        for (int d = 0; d < 16; d++) {
            const float4 kv = kr[d];
            s += q[d].x*kv.x + q[d].y*kv.y + q[d].z*kv.z + q[d].w*kv.w;
        }
        const float e = fexp_shift(s);
        sum += e;
        const float4* vr = reinterpret_cast<const float4*>(base + (size_t)j * 3072 + 2048 + h * 64);
        #pragma unroll
        for (int d = 0; d < 16; d++) {
            const float4 vv = vr[d];
            acc[d].x += e * vv.x; acc[d].y += e * vv.y;
            acc[d].z += e * vv.z; acc[d].w += e * vv.w;
        }
    }
    const float inv = 1.f / sum;
    __half2* op = reinterpret_cast<__half2*>(out + ((size_t)batch * N + row) * 1024 + h * 64);
    #pragma unroll
    for (int d = 0; d < 16; d++) {
        op[d * 2 + 0] = __floats2half2_rn(acc[d].x * inv, acc[d].y * inv);
        op[d * 2 + 1] = __floats2half2_rn(acc[d].z * inv, acc[d].w * inv);
    }
}

// ============================================================
// fp16 tensor-core GEMM (mma.m16n8k16 + ldmatrix):
//   C[M,N] = A[M,K] @ Bt[N,K]^T  (+bias)(+resid)(+gelu)
// 128x128 tile, BK=64 halves (128B swizzled rows), 2-stage cp.async.
// ============================================================
constexpr int STG_B    = 32768;           // A 16KB + B 16KB
constexpr int GEMM_SMEM = 2 * STG_B;

template<bool GELU, bool HALFOUT, bool PERMROW>
__global__ __launch_bounds__(256, 2) void gemm_mma(
    const __half* __restrict__ A, const __half* __restrict__ Bt,
    void* __restrict__ Cv, const float* __restrict__ bias,
    const float* __restrict__ resid, int M, int N, int K)
{
    extern __shared__ float sm[];
    const uint32_t stg = smem_u32(sm);

    const int tid = threadIdx.x;
    const int wid = tid >> 5, lane = tid & 31;
    const int g = lane >> 2, tig = lane & 3;
    const int warpM = wid & 3, warpN = wid >> 2;
    const int bx = blockIdx.x, by = blockIdx.y;
    const int NKB = K >> 6;

    // cp.async: 4×16B chunks for A, 4 for B (swizzled dst). Chunk = 8 halves.
    uint32_t a_s[4], b_s[4];
    const __half *a_g[4], *b_g[4];
    #pragma unroll
    for (int t = 0; t < 4; t++) {
        const int idx = tid + (t << 8);
        const int r = idx >> 3, c = idx & 7;
        const uint32_t sw = (uint32_t)(r * 128 + ((c ^ (r & 7)) << 4));
        a_s[t] = sw;            b_s[t] = sw + 16384;
        a_g[t] = A  + (size_t)(by * 128 + r) * K + c * 8;
        b_g[t] = Bt + (size_t)(bx * 128 + r) * K + c * 8;
    }

    auto load_stage = [&](int s, int kb) {
        const uint32_t sb = stg + s * STG_B;
        const int ko = kb << 6;
        #pragma unroll
        for (int t = 0; t < 4; t++)
            asm volatile("cp.async.cg.shared.global [%0], [%1], 16;" ::
                "r"(sb + a_s[t]), "l"(a_g[t] + ko) : "memory");
        #pragma unroll
        for (int t = 0; t < 4; t++)
            asm volatile("cp.async.cg.shared.global [%0], [%1], 16;" ::
                "r"(sb + b_s[t]), "l"(b_g[t] + ko) : "memory");
    };

    const int lr = lane & 7;
    const int aRow = warpM * 32 + ((lane >> 3) & 1) * 8 + lr;
    const int cbA  = lane >> 4;
    const uint32_t aRx = (uint32_t)(aRow * 128);
    const uint32_t a7  = (uint32_t)(aRow & 7);
    const int bRow = warpN * 64 + (lane >> 4) * 8 + lr;
    const int cbB  = (lane >> 3) & 1;
    const uint32_t bRx = (uint32_t)(bRow * 128);
    const uint32_t b7  = (uint32_t)(bRow & 7);

    float acc[2][8][4];
    #pragma unroll
    for (int mt = 0; mt < 2; mt++)
        #pragma unroll
        for (int nt = 0; nt < 8; nt++)
            #pragma unroll
            for (int i = 0; i < 4; i++) acc[mt][nt][i] = 0.f;

    load_stage(0, 0);
    asm volatile("cp.async.commit_group;" ::: "memory");

    for (int kb = 0; kb < NKB; kb++) {
        if (kb + 1 < NKB) {
            load_stage((kb + 1) & 1, kb + 1);
            asm volatile("cp.async.commit_group;" ::: "memory");
            asm volatile("cp.async.wait_group 1;" ::: "memory");
        } else {
            asm volatile("cp.async.wait_group 0;" ::: "memory");
        }
        __syncthreads();

        const uint32_t sA = stg + (kb & 1) * STG_B;
        const uint32_t sB = sA + 16384;
        #pragma unroll
        for (int ks = 0; ks < 4; ks++) {     // k16 per step, 2 chunks
            uint32_t a[2][4], b[8][2];
            const uint32_t swA = ((uint32_t)(2 * ks + cbA) ^ a7) << 4;
            #pragma unroll
            for (int mt = 0; mt < 2; mt++)
                ldsm4(a[mt][0], a[mt][1], a[mt][2], a[mt][3],
                      sA + aRx + (uint32_t)(mt * 16 * 128) + swA);
            const uint32_t swB = ((uint32_t)(2 * ks + cbB) ^ b7) << 4;
            #pragma unroll
            for (int ntp = 0; ntp < 4; ntp++)
                ldsm4(b[2 * ntp][0], b[2 * ntp][1], b[2 * ntp + 1][0], b[2 * ntp + 1][1],
                      sB + bRx + (uint32_t)(ntp * 16 * 128) + swB);
            #pragma unroll
            for (int mt = 0; mt < 2; mt++)
                #pragma unroll
                for (int nt = 0; nt < 8; nt++)
                    mma_f16(acc[mt][nt], a[mt], b[nt]);
        }
        __syncthreads();
    }

    // ---- epilogue ----
    #pragma unroll
    for (int mt = 0; mt < 2; mt++) {
        #pragma unroll
        for (int half = 0; half < 2; half++) {
            int row = by * 128 + warpM * 32 + mt * 16 + g + half * 8;
            if (PERMROW) {
                const int t = row & 15, s = (row >> 4) & 255, bb = row >> 12;
                row = bb * 4096 + t * 256 + s;
            }
            const float* rp = resid ? resid + (size_t)row * N : nullptr;
            #pragma unroll
            for (int nt = 0; nt < 8; nt++) {
                const int col = bx * 128 + warpN * 64 + nt * 8 + tig * 2;
                float v0 = acc[mt][nt][half * 2 + 0];
                float v1 = acc[mt][nt][half * 2 + 1];
                if (bias) { v0 += bias[col]; v1 += bias[col + 1]; }
                if (rp)   { v0 += rp[col];   v1 += rp[col + 1]; }
                if (GELU) {
                    v0 = 0.5f * v0 * (1.f + erff(v0 * 0.70710678f));
                    v1 = 0.5f * v1 * (1.f + erff(v1 * 0.70710678f));
                }
                if (HALFOUT) {
                    __half* cp = (__half*)Cv + (size_t)row * N + col;
                    *(__half2*)cp = __floats2half2_rn(v0, v1);
                } else {
                    float* cp = (float*)Cv + (size_t)row * N + col;
                    float2 v; v.x = v0; v.y = v1;
                    *(float2*)cp = v;
                }
            }
        }
    }
}

// ============================================================
extern "C" void kernel_launch(void* const* d_in, const int* /*in_sizes*/, int /*n_in*/,
                              void* d_out, int /*out_size*/)
{
    const float* x        = (const float*)d_in[0];
    const float* ns_w     = (const float*)d_in[1];
    const float* ns_b     = (const float*)d_in[2];
    const float* nt_w     = (const float*)d_in[3];
    const float* nt_b     = (const float*)d_in[4];
    const float* nm_w     = (const float*)d_in[5];
    const float* nm_b     = (const float*)d_in[6];
    const float* s_qkv    = (const float*)d_in[7];
    const float* s_qkn_w  = (const float*)d_in[8];
    const float* s_qkn_b  = (const float*)d_in[9];
    const float* s_proj_w = (const float*)d_in[10];
    const float* s_proj_b = (const float*)d_in[11];
    const float* t_qkv    = (const float*)d_in[12];
    const float* t_qkn_w  = (const float*)d_in[13];
    const float* t_qkn_b  = (const float*)d_in[14];
    const float* t_proj_w = (const float*)d_in[15];
    const float* t_proj_b = (const float*)d_in[16];
    const float* fc1_w    = (const float*)d_in[17];
    const float* fc1_b    = (const float*)d_in[18];
    const float* fc2_w    = (const float*)d_in[19];
    const float* fc2_b    = (const float*)d_in[20];
    float* out = (float*)d_out;

    float *xbuf, *qkv;
    __half *xln, *attn, *hbuf;
    __half *wt_sqkv, *wt_sproj, *wt_tqkv, *wt_tproj, *wt_fc1, *wt_fc2;
    cudaGetSymbolAddress((void**)&xbuf, g_xbuf);
    cudaGetSymbolAddress((void**)&xln,  g_xln);
    cudaGetSymbolAddress((void**)&qkv,  g_qkv);
    cudaGetSymbolAddress((void**)&attn, g_attn);
    cudaGetSymbolAddress((void**)&hbuf, g_h);
    cudaGetSymbolAddress((void**)&wt_sqkv,  g_wt_sqkv);
    cudaGetSymbolAddress((void**)&wt_sproj, g_wt_sproj);
    cudaGetSymbolAddress((void**)&wt_tqkv,  g_wt_tqkv);
    cudaGetSymbolAddress((void**)&wt_tproj, g_wt_tproj);
    cudaGetSymbolAddress((void**)&wt_fc1,   g_wt_fc1);
    cudaGetSymbolAddress((void**)&wt_fc2,   g_wt_fc2);

    cudaFuncSetAttribute(attn_tc, cudaFuncAttributeMaxDynamicSharedMemorySize, ATTN_SMEM);
    cudaFuncSetAttribute((const void*)gemm_mma<false, false, false>,
                         cudaFuncAttributeMaxDynamicSharedMemorySize, GEMM_SMEM);
    cudaFuncSetAttribute((const void*)gemm_mma<false, false, true>,
                         cudaFuncAttributeMaxDynamicSharedMemorySize, GEMM_SMEM);
    cudaFuncSetAttribute((const void*)gemm_mma<true,  true,  false>,
                         cudaFuncAttributeMaxDynamicSharedMemorySize, GEMM_SMEM);

    // ---- weight transposes (+ fp16 rounding), once per launch ----
    dim3 tb(32, 8);
    transpose_w<<<dim3(3072/32, 1024/32), tb>>>(s_qkv,    wt_sqkv,  1024, 3072);
    transpose_w<<<dim3(1024/32, 1024/32), tb>>>(s_proj_w, wt_sproj, 1024, 1024);
    transpose_w<<<dim3(3072/32, 1024/32), tb>>>(t_qkv,    wt_tqkv,  1024, 3072);
    transpose_w<<<dim3(1024/32, 1024/32), tb>>>(t_proj_w, wt_tproj, 1024, 1024);
    transpose_w<<<dim3(4096/32, 1024/32), tb>>>(fc1_w,    wt_fc1,   1024, 4096);
    transpose_w<<<dim3(1024/32, 4096/32), tb>>>(fc2_w,    wt_fc2,   4096, 1024);

    const int hl_blocks = (R_ * 3 * H_) / 8;

    // ---- spatial attention block ----
    ln_kernel<false><<<R_, 256>>>(x, xln, ns_w, ns_b);
    gemm_mma<false, false, false><<<dim3(24, 64), 256, GEMM_SMEM>>>(xln, wt_sqkv, qkv, nullptr, nullptr, R_, 3072, 1024);
    headln_kernel<<<hl_blocks, 256>>>(qkv, s_qkn_w, s_qkn_b, SCALE_);
    attn_tc<<<B_ * T_ * H_, 256, ATTN_SMEM>>>(qkv, attn);
    gemm_mma<false, false, false><<<dim3(8, 64), 256, GEMM_SMEM>>>(attn, wt_sproj, xbuf, s_proj_b, x, R_, 1024, 1024);

    // ---- temporal attention block (permutes fused into ln + gemm) ----
    ln_kernel<true><<<R_, 256>>>(xbuf, xln, nt_w, nt_b);
    gemm_mma<false, false, false><<<dim3(24, 64), 256, GEMM_SMEM>>>(xln, wt_tqkv, qkv, nullptr, nullptr, R_, 3072, 1024);
    headln_kernel<<<hl_blocks, 256>>>(qkv, t_qkn_w, t_qkn_b, SCALE_);
    attn16_kernel<<<(B_ * S_ * H_) / 16, 256>>>(qkv, attn);
    gemm_mma<false, false, true><<<dim3(8, 64), 256, GEMM_SMEM>>>(attn, wt_tproj, xbuf, t_proj_b, xbuf, R_, 1024, 1024);

    // ---- MLP ----
    ln_kernel<false><<<R_, 256>>>(xbuf, xln, nm_w, nm_b);
    gemm_mma<true,  true,  false><<<dim3(32, 64), 256, GEMM_SMEM>>>(xln, wt_fc1, hbuf, fc1_b, nullptr, R_, 4096, 1024);
    gemm_mma<false, false, false><<<dim3(8, 64), 256, GEMM_SMEM>>>(hbuf, wt_fc2, out, fc2_b, xbuf, R_, 1024, 4096);
}

// round 9
// speedup vs baseline: 3.6668x; 1.1173x over previous
#include <cuda_runtime.h>
#include <cuda_fp16.h>
#include <cstdint>
#include <math.h>

#define EPSF 1e-5f

constexpr int B_  = 2, T_ = 16, S_ = 256, C_ = 1024, H_ = 16;
constexpr int R_  = B_ * T_ * S_;   // 8192 tokens
constexpr int HID_ = 4 * C_;        // 4096
constexpr float SCALE_ = 8.0f / 64.0f;

// ---- scratch (device globals; no runtime allocation allowed) ----
__device__ float  g_xbuf[R_ * C_];
__device__ __half g_xln [R_ * C_];
__device__ __half g_qkv [R_ * 3 * C_];
__device__ __half g_attn[R_ * C_];
__device__ __half g_h   [R_ * HID_];
// transposed (fp16) weights, [N,K] row-major
__device__ __half g_wt_sqkv [3 * C_ * C_];
__device__ __half g_wt_sproj[C_ * C_];
__device__ __half g_wt_tqkv [3 * C_ * C_];
__device__ __half g_wt_tproj[C_ * C_];
__device__ __half g_wt_fc1  [HID_ * C_];
__device__ __half g_wt_fc2  [C_ * HID_];

__device__ __forceinline__ uint32_t smem_u32(const void* p) {
    uint32_t a;
    asm("{ .reg .u64 t; cvta.to.shared.u64 t, %1; cvt.u32.u64 %0, t; }" : "=r"(a) : "l"(p));
    return a;
}
// e^(s-8) entirely on fma/alu pipes. Valid for s in [-40, 40].
__device__ __forceinline__ float fexp_shift(float s) {
    const float y = fmaf(s, 1.44269504089f, -11.5415603272f);
    const int   i = __float2int_rn(y);
    const float f = y - (float)i;
    float p = fmaf(f, 0.00133335581f, 0.00961812910f);
    p = fmaf(f, p, 0.0555041087f);
    p = fmaf(f, p, 0.240226507f);
    p = fmaf(f, p, 0.693147181f);
    p = fmaf(f, p, 1.0f);
    return __int_as_float(__float_as_int(p) + (i << 23));
}
__device__ __forceinline__ void ldsm4(uint32_t& r0, uint32_t& r1, uint32_t& r2,
                                      uint32_t& r3, uint32_t addr) {
    asm volatile("ldmatrix.sync.aligned.m8n8.x4.b16 {%0,%1,%2,%3}, [%4];"
        : "=r"(r0), "=r"(r1), "=r"(r2), "=r"(r3) : "r"(addr));
}
__device__ __forceinline__ void mma_f16(float c[4], const uint32_t a[4], const uint32_t b[2]) {
    asm volatile("mma.sync.aligned.m16n8k16.row.col.f32.f16.f16.f32 "
        "{%0,%1,%2,%3}, {%4,%5,%6,%7}, {%8,%9}, {%0,%1,%2,%3};"
        : "+f"(c[0]), "+f"(c[1]), "+f"(c[2]), "+f"(c[3])
        : "r"(a[0]), "r"(a[1]), "r"(a[2]), "r"(a[3]), "r"(b[0]), "r"(b[1]));
}
__device__ __forceinline__ uint32_t h2pack(float a, float b) {
    __half2 h = __floats2half2_rn(a, b);
    return *(uint32_t*)&h;
}

// ============================================================
// Weight transpose + fp16 round: in [K,N] float -> out [N,K] half
// ============================================================
__global__ void transpose_w(const float* __restrict__ in, __half* __restrict__ out,
                            int K, int N)
{
    __shared__ float t[32][33];
    const int n0 = blockIdx.x * 32, k0 = blockIdx.y * 32;
    const int x = threadIdx.x, y = threadIdx.y;
    #pragma unroll
    for (int i = 0; i < 32; i += 8)
        t[y + i][x] = in[(size_t)(k0 + y + i) * N + n0 + x];
    __syncthreads();
    #pragma unroll
    for (int i = 0; i < 32; i += 8)
        out[(size_t)(n0 + y + i) * K + k0 + x] = __float2half_rn(t[x][y + i]);
}

// ============================================================
// LayerNorm over C=1024 -> fp16. PERM gathers (B,T,S)->(B,S,T).
// ============================================================
template<bool PERM>
__global__ void ln_kernel(const float* __restrict__ in, __half* __restrict__ out,
                          const float* __restrict__ w, const float* __restrict__ b)
{
    const int row = blockIdx.x, tid = threadIdx.x;
    int in_row = row;
    if (PERM) {
        const int t = row & 15, s = (row >> 4) & 255, bb = row >> 12;
        in_row = bb * 4096 + t * 256 + s;
    }
    const float4 xv = reinterpret_cast<const float4*>(in + (size_t)in_row * 1024)[tid];
    float s  = xv.x + xv.y + xv.z + xv.w;
    float ss = xv.x*xv.x + xv.y*xv.y + xv.z*xv.z + xv.w*xv.w;
    __shared__ float sb[32], ssb[32];
    const int lane = tid & 31, wid = tid >> 5;
    #pragma unroll
    for (int o = 16; o; o >>= 1) {
        s  += __shfl_xor_sync(0xffffffffu, s,  o);
        ss += __shfl_xor_sync(0xffffffffu, ss, o);
    }
    if (lane == 0) { sb[wid] = s; ssb[wid] = ss; }
    __syncthreads();
    if (tid == 0) {
        float ts = 0.f, tss = 0.f;
        #pragma unroll
        for (int i = 0; i < 8; i++) { ts += sb[i]; tss += ssb[i]; }
        float mean = ts * (1.f / 1024.f);
        sb[0]  = mean;
        ssb[0] = rsqrtf(tss * (1.f / 1024.f) - mean * mean + EPSF);
    }
    __syncthreads();
    const float mean = sb[0], rstd = ssb[0];
    const float4 wv = reinterpret_cast<const float4*>(w)[tid];
    const float4 bv = reinterpret_cast<const float4*>(b)[tid];
    uint2 pk;
    pk.x = h2pack((xv.x - mean) * rstd * wv.x + bv.x,
                  (xv.y - mean) * rstd * wv.y + bv.y);
    pk.y = h2pack((xv.z - mean) * rstd * wv.z + bv.z,
                  (xv.w - mean) * rstd * wv.w + bv.w);
    reinterpret_cast<uint2*>(out + (size_t)row * 1024)[tid] = pk;
}

// ============================================================
// Per-head LN (hd=64) on fp16 q,k slices (v untouched).
// ============================================================
__global__ void headln_kernel(__half* __restrict__ qkv, const float* __restrict__ w,
                              const float* __restrict__ b, float qscale)
{
    const int gw   = (blockIdx.x * blockDim.x + threadIdx.x) >> 5;
    const int lane = threadIdx.x & 31;
    const int r     = gw >> 5;
    const int rem   = gw & 31;
    const int which = rem >> 4;      // 0 q, 1 k
    const int h     = rem & 15;
    __half* p = qkv + (size_t)r * 3072 + which * 1024 + h * 64;
    const float v0 = __half2float(p[lane]), v1 = __half2float(p[lane + 32]);
    float s = v0 + v1, ss = v0*v0 + v1*v1;
    #pragma unroll
    for (int o = 16; o; o >>= 1) {
        s  += __shfl_xor_sync(0xffffffffu, s,  o);
        ss += __shfl_xor_sync(0xffffffffu, ss, o);
    }
    const float mean = s * (1.f / 64.f);
    const float rstd = rsqrtf(ss * (1.f / 64.f) - mean * mean + EPSF);
    const float sc = which ? 1.f : qscale;
    p[lane]      = __float2half_rn(((v0 - mean) * rstd * w[lane]      + b[lane])      * sc);
    p[lane + 32] = __float2half_rn(((v1 - mean) * rstd * w[lane + 32] + b[lane + 32]) * sc);
}

// ============================================================
// Spatial attention, all-fp16 tensor-core path.
// Q,K staged [256 rows x 128B] swizzled; V transposed [64 d x 512B].
// P.V A-fragments come straight from S accumulators (no shuffles).
// ============================================================
constexpr int ATTN_SMEM = 3 * 32768;   // 96 KB

__global__ __launch_bounds__(256) void attn_tc(const __half* __restrict__ qkv,
                                               __half* __restrict__ out)
{
    extern __shared__ float smf[];
    char* smc = (char*)smf;
    const uint32_t Qs = smem_u32(smf);
    const uint32_t Ks = Qs + 32768;
    const uint32_t Vt = Qs + 65536;

    const int tid = threadIdx.x, wid = tid >> 5, lane = tid & 31;
    const int g = lane >> 2, tig = lane & 3;
    const int bh = blockIdx.x, h = bh & 15, batch = bh >> 4;
    const __half* base = qkv + (size_t)batch * 256 * 3072;

    // ---- stage Q, K (swizzled 128B rows) and V (transposed, 512B rows) ----
    #pragma unroll
    for (int t = 0; t < 8; t++) {
        const int idx = tid + (t << 8);          // 0..2047
        const int r = idx >> 3, c = idx & 7;     // key/query row, 16B chunk
        const uint32_t dst = (uint32_t)(r * 128 + ((c ^ (r & 7)) << 4));
        const uint4 qv = *(const uint4*)(base + (size_t)r * 3072 + h * 64 + c * 8);
        *(uint4*)(smc + dst) = qv;
        const uint4 kv = *(const uint4*)(base + (size_t)r * 3072 + 1024 + h * 64 + c * 8);
        *(uint4*)(smc + 32768 + dst) = kv;
        uint4 vv = *(const uint4*)(base + (size_t)r * 3072 + 2048 + h * 64 + c * 8);
        __half hv[8];
        *(uint4*)hv = vv;
        const int kc = r >> 3, kb = r & 7;
        #pragma unroll
        for (int i = 0; i < 8; i++) {
            const int d = c * 8 + i;
            const uint32_t vc = (uint32_t)((kc & 24) | ((kc ^ d) & 7));
            *(__half*)(smc + 65536 + d * 512 + (vc << 4) + kb * 2) = hv[i];
        }
    }
    __syncthreads();

    // ---- Q fragments (A-side, m16n8k16), resident ----
    const int lr = lane & 7;
    const int aRow = wid * 32 + ((lane >> 3) & 1) * 8 + lr;
    const int cbA = lane >> 4;
    uint32_t qf[2][4][4];
    #pragma unroll
    for (int mt = 0; mt < 2; mt++)
        #pragma unroll
        for (int ks = 0; ks < 4; ks++)
            ldsm4(qf[mt][ks][0], qf[mt][ks][1], qf[mt][ks][2], qf[mt][ks][3],
                  Qs + (uint32_t)((aRow + mt * 16) * 128) +
                  (((uint32_t)(2 * ks + cbA) ^ (uint32_t)lr) << 4));

    const int bRow = (lane >> 4) * 8 + lr;
    const int cbB = (lane >> 3) & 1;

    float o[2][8][4];
    float rs[2][2] = {{0.f, 0.f}, {0.f, 0.f}};
    #pragma unroll
    for (int mt = 0; mt < 2; mt++)
        #pragma unroll
        for (int no = 0; no < 8; no++)
            #pragma unroll
            for (int i = 0; i < 4; i++) o[mt][no][i] = 0.f;

    for (int tile = 0; tile < 8; tile++) {
        // ---- S = Q @ K^T (32 keys = 4 n8 tiles, 4 k16 steps) ----
        float s[2][4][4];
        #pragma unroll
        for (int mt = 0; mt < 2; mt++)
            #pragma unroll
            for (int nt = 0; nt < 4; nt++)
                #pragma unroll
                for (int i = 0; i < 4; i++) s[mt][nt][i] = 0.f;
        #pragma unroll
        for (int ks = 0; ks < 4; ks++) {
            uint32_t kb_[4][2];
            #pragma unroll
            for (int ntp = 0; ntp < 2; ntp++)
                ldsm4(kb_[2*ntp][0], kb_[2*ntp][1], kb_[2*ntp+1][0], kb_[2*ntp+1][1],
                      Ks + (uint32_t)((tile * 32 + bRow + ntp * 16) * 128) +
                      (((uint32_t)(2 * ks + cbB) ^ (uint32_t)lr) << 4));
            #pragma unroll
            for (int mt = 0; mt < 2; mt++)
                #pragma unroll
                for (int nt = 0; nt < 4; nt++)
                    mma_f16(s[mt][nt], qf[mt][ks], kb_[nt]);
        }
        // ---- softmax weights (fixed shift) + row-sum partials ----
        #pragma unroll
        for (int mt = 0; mt < 2; mt++)
            #pragma unroll
            for (int nt = 0; nt < 4; nt++)
                #pragma unroll
                for (int i = 0; i < 4; i++) {
                    const float e = fexp_shift(s[mt][nt][i]);
                    rs[mt][i >> 1] += e;
                    s[mt][nt][i] = e;
                }
        // ---- O += P @ V : A-fragments straight from S accumulators ----
        #pragma unroll
        for (int kk = 0; kk < 2; kk++) {
            uint32_t vb[8][2];
            const uint32_t c0 = (uint32_t)(tile * 4 + kk * 2 + cbB);
            #pragma unroll
            for (int ntp = 0; ntp < 4; ntp++) {
                const uint32_t row = (uint32_t)(bRow + ntp * 16);
                const uint32_t vc = (c0 & 24) | ((c0 ^ (uint32_t)lr) & 7);
                ldsm4(vb[2*ntp][0], vb[2*ntp][1], vb[2*ntp+1][0], vb[2*ntp+1][1],
                      Vt + row * 512 + (vc << 4));
            }
            #pragma unroll
            for (int mt = 0; mt < 2; mt++) {
                uint32_t pa[4];
                pa[0] = h2pack(s[mt][2*kk][0],   s[mt][2*kk][1]);
                pa[1] = h2pack(s[mt][2*kk][2],   s[mt][2*kk][3]);
                pa[2] = h2pack(s[mt][2*kk+1][0], s[mt][2*kk+1][1]);
                pa[3] = h2pack(s[mt][2*kk+1][2], s[mt][2*kk+1][3]);
                #pragma unroll
                for (int no = 0; no < 8; no++)
                    mma_f16(o[mt][no], pa, vb[no]);
            }
        }
    }

    // ---- normalize & write fp16 ----
    #pragma unroll
    for (int mt = 0; mt < 2; mt++)
        #pragma unroll
        for (int i = 0; i < 2; i++) {
            float v = rs[mt][i];
            v += __shfl_xor_sync(0xffffffffu, v, 1);
            v += __shfl_xor_sync(0xffffffffu, v, 2);
            rs[mt][i] = 1.f / v;
        }
    #pragma unroll
    for (int mt = 0; mt < 2; mt++) {
        const int r0 = wid * 32 + mt * 16 + g;
        __half* p0 = out + ((size_t)batch * 256 + r0) * 1024 + h * 64;
        __half* p1 = p0 + 8 * 1024;
        #pragma unroll
        for (int no = 0; no < 8; no++) {
            *(uint32_t*)(p0 + no * 8 + tig * 2) =
                h2pack(o[mt][no][0] * rs[mt][0], o[mt][no][1] * rs[mt][0]);
            *(uint32_t*)(p1 + no * 8 + tig * 2) =
                h2pack(o[mt][no][2] * rs[mt][1], o[mt][no][3] * rs[mt][1]);
        }
    }
}

// ============================================================
// Temporal attention (N=16), fp16 in/out, fp32 accumulate.
// ============================================================
__global__ void attn16_kernel(const __half* __restrict__ qkv, __half* __restrict__ out)
{
    constexpr int N = 16;
    const int tid = threadIdx.x;
    const int bh = blockIdx.x * 16 + (tid >> 4);
    const int h = bh & 15;
    const int batch = bh >> 4;
    const int row = tid & 15;
    const __half* base = qkv + (size_t)batch * N * 3072;

    __half2 q2[32];
    {
        const uint4* qp = reinterpret_cast<const uint4*>(base + (size_t)row * 3072 + h * 64);
        #pragma unroll
        for (int c = 0; c < 8; c++) *(uint4*)(q2 + c * 4) = qp[c];
    }

    float2 acc[32];
    #pragma unroll
    for (int d = 0; d < 32; d++) acc[d] = make_float2(0.f, 0.f);
    float sum = 0.f;
    #pragma unroll
    for (int j = 0; j < N; j++) {
        __half2 k2[32];
        const uint4* kp = reinterpret_cast<const uint4*>(base + (size_t)j * 3072 + 1024 + h * 64);
        #pragma unroll
        for (int c = 0; c < 8; c++) *(uint4*)(k2 + c * 4) = kp[c];
        float s = 0.f;
        #pragma unroll
        for (int d = 0; d < 32; d++) {
            const float2 qd = __half22float2(q2[d]);
            const float2 kd = __half22float2(k2[d]);
            s += qd.x * kd.x + qd.y * kd.y;
        }
        const float e = fexp_shift(s);
        sum += e;
        __half2 v2[32];
        const uint4* vp = reinterpret_cast<const uint4*>(base + (size_t)j * 3072 + 2048 + h * 64);
        #pragma unroll
        for (int c = 0; c < 8; c++) *(uint4*)(v2 + c * 4) = vp[c];
        #pragma unroll
        for (int d = 0; d < 32; d++) {
            const float2 vd = __half22float2(v2[d]);
            acc[d].x += e * vd.x;
            acc[d].y += e * vd.y;
        }
    }
    const float inv = 1.f / sum;
    uint32_t* op = reinterpret_cast<uint32_t*>(out + ((size_t)batch * N + row) * 1024 + h * 64);
    #pragma unroll
    for (int d = 0; d < 32; d++)
        op[d] = h2pack(acc[d].x * inv, acc[d].y * inv);
}

// ============================================================
// fp16 tensor-core GEMM (unchanged R8 structure):
//   C[M,N] = A[M,K] @ Bt[N,K]^T  (+bias)(+resid)(+gelu)
// ============================================================
constexpr int STG_B    = 32768;
constexpr int GEMM_SMEM = 2 * STG_B;

template<bool GELU, bool HALFOUT, bool PERMROW>
__global__ __launch_bounds__(256, 2) void gemm_mma(
    const __half* __restrict__ A, const __half* __restrict__ Bt,
    void* __restrict__ Cv, const float* __restrict__ bias,
    const float* __restrict__ resid, int M, int N, int K)
{
    extern __shared__ float sm[];
    const uint32_t stg = smem_u32(sm);

    const int tid = threadIdx.x;
    const int wid = tid >> 5, lane = tid & 31;
    const int g = lane >> 2, tig = lane & 3;
    const int warpM = wid & 3, warpN = wid >> 2;
    const int bx = blockIdx.x, by = blockIdx.y;
    const int NKB = K >> 6;

    uint32_t a_s[4], b_s[4];
    const __half *a_g[4], *b_g[4];
    #pragma unroll
    for (int t = 0; t < 4; t++) {
        const int idx = tid + (t << 8);
        const int r = idx >> 3, c = idx & 7;
        const uint32_t sw = (uint32_t)(r * 128 + ((c ^ (r & 7)) << 4));
        a_s[t] = sw;            b_s[t] = sw + 16384;
        a_g[t] = A  + (size_t)(by * 128 + r) * K + c * 8;
        b_g[t] = Bt + (size_t)(bx * 128 + r) * K + c * 8;
    }

    auto load_stage = [&](int s, int kb) {
        const uint32_t sb = stg + s * STG_B;
        const int ko = kb << 6;
        #pragma unroll
        for (int t = 0; t < 4; t++)
            asm volatile("cp.async.cg.shared.global [%0], [%1], 16;" ::
                "r"(sb + a_s[t]), "l"(a_g[t] + ko) : "memory");
        #pragma unroll
        for (int t = 0; t < 4; t++)
            asm volatile("cp.async.cg.shared.global [%0], [%1], 16;" ::
                "r"(sb + b_s[t]), "l"(b_g[t] + ko) : "memory");
    };

    const int lr = lane & 7;
    const int aRow = warpM * 32 + ((lane >> 3) & 1) * 8 + lr;
    const int cbA  = lane >> 4;
    const uint32_t aRx = (uint32_t)(aRow * 128);
    const uint32_t a7  = (uint32_t)(aRow & 7);
    const int bRow = warpN * 64 + (lane >> 4) * 8 + lr;
    const int cbB  = (lane >> 3) & 1;
    const uint32_t bRx = (uint32_t)(bRow * 128);
    const uint32_t b7  = (uint32_t)(bRow & 7);

    float acc[2][8][4];
    #pragma unroll
    for (int mt = 0; mt < 2; mt++)
        #pragma unroll
        for (int nt = 0; nt < 8; nt++)
            #pragma unroll
            for (int i = 0; i < 4; i++) acc[mt][nt][i] = 0.f;

    load_stage(0, 0);
    asm volatile("cp.async.commit_group;" ::: "memory");

    for (int kb = 0; kb < NKB; kb++) {
        if (kb + 1 < NKB) {
            load_stage((kb + 1) & 1, kb + 1);
            asm volatile("cp.async.commit_group;" ::: "memory");
            asm volatile("cp.async.wait_group 1;" ::: "memory");
        } else {
            asm volatile("cp.async.wait_group 0;" ::: "memory");
        }
        __syncthreads();

        const uint32_t sA = stg + (kb & 1) * STG_B;
        const uint32_t sB = sA + 16384;
        #pragma unroll
        for (int ks = 0; ks < 4; ks++) {
            uint32_t a[2][4], b[8][2];
            const uint32_t swA = ((uint32_t)(2 * ks + cbA) ^ a7) << 4;
            #pragma unroll
            for (int mt = 0; mt < 2; mt++)
                ldsm4(a[mt][0], a[mt][1], a[mt][2], a[mt][3],
                      sA + aRx + (uint32_t)(mt * 16 * 128) + swA);
            const uint32_t swB = ((uint32_t)(2 * ks + cbB) ^ b7) << 4;
            #pragma unroll
            for (int ntp = 0; ntp < 4; ntp++)
                ldsm4(b[2 * ntp][0], b[2 * ntp][1], b[2 * ntp + 1][0], b[2 * ntp + 1][1],
                      sB + bRx + (uint32_t)(ntp * 16 * 128) + swB);
            #pragma unroll
            for (int mt = 0; mt < 2; mt++)
                #pragma unroll
                for (int nt = 0; nt < 8; nt++)
                    mma_f16(acc[mt][nt], a[mt], b[nt]);
        }
        __syncthreads();
    }

    #pragma unroll
    for (int mt = 0; mt < 2; mt++) {
        #pragma unroll
        for (int half = 0; half < 2; half++) {
            int row = by * 128 + warpM * 32 + mt * 16 + g + half * 8;
            if (PERMROW) {
                const int t = row & 15, s = (row >> 4) & 255, bb = row >> 12;
                row = bb * 4096 + t * 256 + s;
            }
            const float* rp = resid ? resid + (size_t)row * N : nullptr;
            #pragma unroll
            for (int nt = 0; nt < 8; nt++) {
                const int col = bx * 128 + warpN * 64 + nt * 8 + tig * 2;
                float v0 = acc[mt][nt][half * 2 + 0];
                float v1 = acc[mt][nt][half * 2 + 1];
                if (bias) { v0 += bias[col]; v1 += bias[col + 1]; }
                if (rp)   { v0 += rp[col];   v1 += rp[col + 1]; }
                if (GELU) {
                    v0 = 0.5f * v0 * (1.f + erff(v0 * 0.70710678f));
                    v1 = 0.5f * v1 * (1.f + erff(v1 * 0.70710678f));
                }
                if (HALFOUT) {
                    __half* cp = (__half*)Cv + (size_t)row * N + col;
                    *(uint32_t*)cp = h2pack(v0, v1);
                } else {
                    float* cp = (float*)Cv + (size_t)row * N + col;
                    float2 v; v.x = v0; v.y = v1;
                    *(float2*)cp = v;
                }
            }
        }
    }
}

// ============================================================
extern "C" void kernel_launch(void* const* d_in, const int* /*in_sizes*/, int /*n_in*/,
                              void* d_out, int /*out_size*/)
{
    const float* x        = (const float*)d_in[0];
    const float* ns_w     = (const float*)d_in[1];
    const float* ns_b     = (const float*)d_in[2];
    const float* nt_w     = (const float*)d_in[3];
    const float* nt_b     = (const float*)d_in[4];
    const float* nm_w     = (const float*)d_in[5];
    const float* nm_b     = (const float*)d_in[6];
    const float* s_qkv    = (const float*)d_in[7];
    const float* s_qkn_w  = (const float*)d_in[8];
    const float* s_qkn_b  = (const float*)d_in[9];
    const float* s_proj_w = (const float*)d_in[10];
    const float* s_proj_b = (const float*)d_in[11];
    const float* t_qkv    = (const float*)d_in[12];
    const float* t_qkn_w  = (const float*)d_in[13];
    const float* t_qkn_b  = (const float*)d_in[14];
    const float* t_proj_w = (const float*)d_in[15];
    const float* t_proj_b = (const float*)d_in[16];
    const float* fc1_w    = (const float*)d_in[17];
    const float* fc1_b    = (const float*)d_in[18];
    const float* fc2_w    = (const float*)d_in[19];
    const float* fc2_b    = (const float*)d_in[20];
    float* out = (float*)d_out;

    float *xbuf;
    __half *xln, *qkv, *attn, *hbuf;
    __half *wt_sqkv, *wt_sproj, *wt_tqkv, *wt_tproj, *wt_fc1, *wt_fc2;
    cudaGetSymbolAddress((void**)&xbuf, g_xbuf);
    cudaGetSymbolAddress((void**)&xln,  g_xln);
    cudaGetSymbolAddress((void**)&qkv,  g_qkv);
    cudaGetSymbolAddress((void**)&attn, g_attn);
    cudaGetSymbolAddress((void**)&hbuf, g_h);
    cudaGetSymbolAddress((void**)&wt_sqkv,  g_wt_sqkv);
    cudaGetSymbolAddress((void**)&wt_sproj, g_wt_sproj);
    cudaGetSymbolAddress((void**)&wt_tqkv,  g_wt_tqkv);
    cudaGetSymbolAddress((void**)&wt_tproj, g_wt_tproj);
    cudaGetSymbolAddress((void**)&wt_fc1,   g_wt_fc1);
    cudaGetSymbolAddress((void**)&wt_fc2,   g_wt_fc2);

    cudaFuncSetAttribute(attn_tc, cudaFuncAttributeMaxDynamicSharedMemorySize, ATTN_SMEM);
    cudaFuncSetAttribute((const void*)gemm_mma<false, false, false>,
                         cudaFuncAttributeMaxDynamicSharedMemorySize, GEMM_SMEM);
    cudaFuncSetAttribute((const void*)gemm_mma<false, true,  false>,
                         cudaFuncAttributeMaxDynamicSharedMemorySize, GEMM_SMEM);
    cudaFuncSetAttribute((const void*)gemm_mma<false, false, true>,
                         cudaFuncAttributeMaxDynamicSharedMemorySize, GEMM_SMEM);
    cudaFuncSetAttribute((const void*)gemm_mma<true,  true,  false>,
                         cudaFuncAttributeMaxDynamicSharedMemorySize, GEMM_SMEM);

    // ---- weight transposes (+ fp16 rounding), once per launch ----
    dim3 tb(32, 8);
    transpose_w<<<dim3(3072/32, 1024/32), tb>>>(s_qkv,    wt_sqkv,  1024, 3072);
    transpose_w<<<dim3(1024/32, 1024/32), tb>>>(s_proj_w, wt_sproj, 1024, 1024);
    transpose_w<<<dim3(3072/32, 1024/32), tb>>>(t_qkv,    wt_tqkv,  1024, 3072);
    transpose_w<<<dim3(1024/32, 1024/32), tb>>>(t_proj_w, wt_tproj, 1024, 1024);
    transpose_w<<<dim3(4096/32, 1024/32), tb>>>(fc1_w,    wt_fc1,   1024, 4096);
    transpose_w<<<dim3(1024/32, 4096/32), tb>>>(fc2_w,    wt_fc2,   4096, 1024);

    const int hl_blocks = (R_ * 2 * H_) / 8;   // 32 vectors/row, 8 warps/block

    // ---- spatial attention block ----
    ln_kernel<false><<<R_, 256>>>(x, xln, ns_w, ns_b);
    gemm_mma<false, true, false><<<dim3(24, 64), 256, GEMM_SMEM>>>(xln, wt_sqkv, qkv, nullptr, nullptr, R_, 3072, 1024);
    headln_kernel<<<hl_blocks, 256>>>(qkv, s_qkn_w, s_qkn_b, SCALE_);
    attn_tc<<<B_ * T_ * H_, 256, ATTN_SMEM>>>(qkv, attn);
    gemm_mma<false, false, false><<<dim3(8, 64), 256, GEMM_SMEM>>>(attn, wt_sproj, xbuf, s_proj_b, x, R_, 1024, 1024);

    // ---- temporal attention block (permutes fused into ln + gemm) ----
    ln_kernel<true><<<R_, 256>>>(xbuf, xln, nt_w, nt_b);
    gemm_mma<false, true, false><<<dim3(24, 64), 256, GEMM_SMEM>>>(xln, wt_tqkv, qkv, nullptr, nullptr, R_, 3072, 1024);
    headln_kernel<<<hl_blocks, 256>>>(qkv, t_qkn_w, t_qkn_b, SCALE_);
    attn16_kernel<<<(B_ * S_ * H_) / 16, 256>>>(qkv, attn);
    gemm_mma<false, false, true><<<dim3(8, 64), 256, GEMM_SMEM>>>(attn, wt_tproj, xbuf, t_proj_b, xbuf, R_, 1024, 1024);

    // ---- MLP ----
    ln_kernel<false><<<R_, 256>>>(xbuf, xln, nm_w, nm_b);
    gemm_mma<true,  true,  false><<<dim3(32, 64), 256, GEMM_SMEM>>>(xln, wt_fc1, hbuf, fc1_b, nullptr, R_, 4096, 1024);
    gemm_mma<false, false, false><<<dim3(8, 64), 256, GEMM_SMEM>>>(hbuf, wt_fc2, out, fc2_b, xbuf, R_, 1024, 4096);
}

// round 10
// speedup vs baseline: 3.8027x; 1.0371x over previous
#include <cuda_runtime.h>
#include <cuda_fp16.h>
#include <cstdint>
#include <math.h>

#define EPSF 1e-5f

constexpr int B_  = 2, T_ = 16, S_ = 256, C_ = 1024, H_ = 16;
constexpr int R_  = B_ * T_ * S_;   // 8192 tokens
constexpr int HID_ = 4 * C_;        // 4096
constexpr float SCALE_ = 8.0f / 64.0f;

// ---- scratch (device globals; no runtime allocation allowed) ----
__device__ float  g_xbuf[R_ * C_];
__device__ __half g_xln [R_ * C_];
__device__ __half g_qkv [R_ * 3 * C_];
__device__ __half g_attn[R_ * C_];
__device__ __half g_h   [R_ * HID_];
// transposed (fp16) weights, [N,K] row-major
__device__ __half g_wt_sqkv [3 * C_ * C_];
__device__ __half g_wt_sproj[C_ * C_];
__device__ __half g_wt_tqkv [3 * C_ * C_];
__device__ __half g_wt_tproj[C_ * C_];
__device__ __half g_wt_fc1  [HID_ * C_];
__device__ __half g_wt_fc2  [C_ * HID_];

__device__ __forceinline__ uint32_t smem_u32(const void* p) {
    uint32_t a;
    asm("{ .reg .u64 t; cvta.to.shared.u64 t, %1; cvt.u32.u64 %0, t; }" : "=r"(a) : "l"(p));
    return a;
}
// e^(s-8) entirely on fma/alu pipes. Valid for s in [-40, 40].
__device__ __forceinline__ float fexp_shift(float s) {
    const float y = fmaf(s, 1.44269504089f, -11.5415603272f);
    const int   i = __float2int_rn(y);
    const float f = y - (float)i;
    float p = fmaf(f, 0.00133335581f, 0.00961812910f);
    p = fmaf(f, p, 0.0555041087f);
    p = fmaf(f, p, 0.240226507f);
    p = fmaf(f, p, 0.693147181f);
    p = fmaf(f, p, 1.0f);
    return __int_as_float(__float_as_int(p) + (i << 23));
}
__device__ __forceinline__ void ldsm4(uint32_t& r0, uint32_t& r1, uint32_t& r2,
                                      uint32_t& r3, uint32_t addr) {
    asm volatile("ldmatrix.sync.aligned.m8n8.x4.b16 {%0,%1,%2,%3}, [%4];"
        : "=r"(r0), "=r"(r1), "=r"(r2), "=r"(r3) : "r"(addr));
}
__device__ __forceinline__ void mma_f16(float c[4], const uint32_t a[4], const uint32_t b[2]) {
    asm volatile("mma.sync.aligned.m16n8k16.row.col.f32.f16.f16.f32 "
        "{%0,%1,%2,%3}, {%4,%5,%6,%7}, {%8,%9}, {%0,%1,%2,%3};"
        : "+f"(c[0]), "+f"(c[1]), "+f"(c[2]), "+f"(c[3])
        : "r"(a[0]), "r"(a[1]), "r"(a[2]), "r"(a[3]), "r"(b[0]), "r"(b[1]));
}
__device__ __forceinline__ uint32_t h2pack(float a, float b) {
    __half2 h = __floats2half2_rn(a, b);
    return *(uint32_t*)&h;
}

// ============================================================
// Weight transpose + fp16 round: in [K,N] float -> out [N,K] half
// ============================================================
__global__ void transpose_w(const float* __restrict__ in, __half* __restrict__ out,
                            int K, int N)
{
    __shared__ float t[32][33];
    const int n0 = blockIdx.x * 32, k0 = blockIdx.y * 32;
    const int x = threadIdx.x, y = threadIdx.y;
    #pragma unroll
    for (int i = 0; i < 32; i += 8)
        t[y + i][x] = in[(size_t)(k0 + y + i) * N + n0 + x];
    __syncthreads();
    #pragma unroll
    for (int i = 0; i < 32; i += 8)
        out[(size_t)(n0 + y + i) * K + k0 + x] = __float2half_rn(t[x][y + i]);
}

// ============================================================
// LayerNorm over C=1024 -> fp16. PERM gathers (B,T,S)->(B,S,T).
// ============================================================
template<bool PERM>
__global__ void ln_kernel(const float* __restrict__ in, __half* __restrict__ out,
                          const float* __restrict__ w, const float* __restrict__ b)
{
    const int row = blockIdx.x, tid = threadIdx.x;
    int in_row = row;
    if (PERM) {
        const int t = row & 15, s = (row >> 4) & 255, bb = row >> 12;
        in_row = bb * 4096 + t * 256 + s;
    }
    const float4 xv = reinterpret_cast<const float4*>(in + (size_t)in_row * 1024)[tid];
    float s  = xv.x + xv.y + xv.z + xv.w;
    float ss = xv.x*xv.x + xv.y*xv.y + xv.z*xv.z + xv.w*xv.w;
    __shared__ float sb[32], ssb[32];
    const int lane = tid & 31, wid = tid >> 5;
    #pragma unroll
    for (int o = 16; o; o >>= 1) {
        s  += __shfl_xor_sync(0xffffffffu, s,  o);
        ss += __shfl_xor_sync(0xffffffffu, ss, o);
    }
    if (lane == 0) { sb[wid] = s; ssb[wid] = ss; }
    __syncthreads();
    if (tid == 0) {
        float ts = 0.f, tss = 0.f;
        #pragma unroll
        for (int i = 0; i < 8; i++) { ts += sb[i]; tss += ssb[i]; }
        float mean = ts * (1.f / 1024.f);
        sb[0]  = mean;
        ssb[0] = rsqrtf(tss * (1.f / 1024.f) - mean * mean + EPSF);
    }
    __syncthreads();
    const float mean = sb[0], rstd = ssb[0];
    const float4 wv = reinterpret_cast<const float4*>(w)[tid];
    const float4 bv = reinterpret_cast<const float4*>(b)[tid];
    uint2 pk;
    pk.x = h2pack((xv.x - mean) * rstd * wv.x + bv.x,
                  (xv.y - mean) * rstd * wv.y + bv.y);
    pk.y = h2pack((xv.z - mean) * rstd * wv.z + bv.z,
                  (xv.w - mean) * rstd * wv.w + bv.w);
    reinterpret_cast<uint2*>(out + (size_t)row * 1024)[tid] = pk;
}

// ============================================================
// Spatial attention, all-fp16 tensor-core path (unchanged R9).
// ============================================================
constexpr int ATTN_SMEM = 3 * 32768;   // 96 KB

__global__ __launch_bounds__(256) void attn_tc(const __half* __restrict__ qkv,
                                               __half* __restrict__ out)
{
    extern __shared__ float smf[];
    char* smc = (char*)smf;
    const uint32_t Qs = smem_u32(smf);
    const uint32_t Ks = Qs + 32768;
    const uint32_t Vt = Qs + 65536;

    const int tid = threadIdx.x, wid = tid >> 5, lane = tid & 31;
    const int g = lane >> 2, tig = lane & 3;
    const int bh = blockIdx.x, h = bh & 15, batch = bh >> 4;
    const __half* base = qkv + (size_t)batch * 256 * 3072;

    #pragma unroll
    for (int t = 0; t < 8; t++) {
        const int idx = tid + (t << 8);
        const int r = idx >> 3, c = idx & 7;
        const uint32_t dst = (uint32_t)(r * 128 + ((c ^ (r & 7)) << 4));
        const uint4 qv = *(const uint4*)(base + (size_t)r * 3072 + h * 64 + c * 8);
        *(uint4*)(smc + dst) = qv;
        const uint4 kv = *(const uint4*)(base + (size_t)r * 3072 + 1024 + h * 64 + c * 8);
        *(uint4*)(smc + 32768 + dst) = kv;
        uint4 vv = *(const uint4*)(base + (size_t)r * 3072 + 2048 + h * 64 + c * 8);
        __half hv[8];
        *(uint4*)hv = vv;
        const int kc = r >> 3, kb = r & 7;
        #pragma unroll
        for (int i = 0; i < 8; i++) {
            const int d = c * 8 + i;
            const uint32_t vc = (uint32_t)((kc & 24) | ((kc ^ d) & 7));
            *(__half*)(smc + 65536 + d * 512 + (vc << 4) + kb * 2) = hv[i];
        }
    }
    __syncthreads();

    const int lr = lane & 7;
    const int aRow = wid * 32 + ((lane >> 3) & 1) * 8 + lr;
    const int cbA = lane >> 4;
    uint32_t qf[2][4][4];
    #pragma unroll
    for (int mt = 0; mt < 2; mt++)
        #pragma unroll
        for (int ks = 0; ks < 4; ks++)
            ldsm4(qf[mt][ks][0], qf[mt][ks][1], qf[mt][ks][2], qf[mt][ks][3],
                  Qs + (uint32_t)((aRow + mt * 16) * 128) +
                  (((uint32_t)(2 * ks + cbA) ^ (uint32_t)lr) << 4));

    const int bRow = (lane >> 4) * 8 + lr;
    const int cbB = (lane >> 3) & 1;

    float o[2][8][4];
    float rs[2][2] = {{0.f, 0.f}, {0.f, 0.f}};
    #pragma unroll
    for (int mt = 0; mt < 2; mt++)
        #pragma unroll
        for (int no = 0; no < 8; no++)
            #pragma unroll
            for (int i = 0; i < 4; i++) o[mt][no][i] = 0.f;

    for (int tile = 0; tile < 8; tile++) {
        float s[2][4][4];
        #pragma unroll
        for (int mt = 0; mt < 2; mt++)
            #pragma unroll
            for (int nt = 0; nt < 4; nt++)
                #pragma unroll
                for (int i = 0; i < 4; i++) s[mt][nt][i] = 0.f;
        #pragma unroll
        for (int ks = 0; ks < 4; ks++) {
            uint32_t kb_[4][2];
            #pragma unroll
            for (int ntp = 0; ntp < 2; ntp++)
                ldsm4(kb_[2*ntp][0], kb_[2*ntp][1], kb_[2*ntp+1][0], kb_[2*ntp+1][1],
                      Ks + (uint32_t)((tile * 32 + bRow + ntp * 16) * 128) +
                      (((uint32_t)(2 * ks + cbB) ^ (uint32_t)lr) << 4));
            #pragma unroll
            for (int mt = 0; mt < 2; mt++)
                #pragma unroll
                for (int nt = 0; nt < 4; nt++)
                    mma_f16(s[mt][nt], qf[mt][ks], kb_[nt]);
        }
        #pragma unroll
        for (int mt = 0; mt < 2; mt++)
            #pragma unroll
            for (int nt = 0; nt < 4; nt++)
                #pragma unroll
                for (int i = 0; i < 4; i++) {
                    const float e = fexp_shift(s[mt][nt][i]);
                    rs[mt][i >> 1] += e;
                    s[mt][nt][i] = e;
                }
        #pragma unroll
        for (int kk = 0; kk < 2; kk++) {
            uint32_t vb[8][2];
            const uint32_t c0 = (uint32_t)(tile * 4 + kk * 2 + cbB);
            #pragma unroll
            for (int ntp = 0; ntp < 4; ntp++) {
                const uint32_t row = (uint32_t)(bRow + ntp * 16);
                const uint32_t vc = (c0 & 24) | ((c0 ^ (uint32_t)lr) & 7);
                ldsm4(vb[2*ntp][0], vb[2*ntp][1], vb[2*ntp+1][0], vb[2*ntp+1][1],
                      Vt + row * 512 + (vc << 4));
            }
            #pragma unroll
            for (int mt = 0; mt < 2; mt++) {
                uint32_t pa[4];
                pa[0] = h2pack(s[mt][2*kk][0],   s[mt][2*kk][1]);
                pa[1] = h2pack(s[mt][2*kk][2],   s[mt][2*kk][3]);
                pa[2] = h2pack(s[mt][2*kk+1][0], s[mt][2*kk+1][1]);
                pa[3] = h2pack(s[mt][2*kk+1][2], s[mt][2*kk+1][3]);
                #pragma unroll
                for (int no = 0; no < 8; no++)
                    mma_f16(o[mt][no], pa, vb[no]);
            }
        }
    }

    #pragma unroll
    for (int mt = 0; mt < 2; mt++)
        #pragma unroll
        for (int i = 0; i < 2; i++) {
            float v = rs[mt][i];
            v += __shfl_xor_sync(0xffffffffu, v, 1);
            v += __shfl_xor_sync(0xffffffffu, v, 2);
            rs[mt][i] = 1.f / v;
        }
    #pragma unroll
    for (int mt = 0; mt < 2; mt++) {
        const int r0 = wid * 32 + mt * 16 + g;
        __half* p0 = out + ((size_t)batch * 256 + r0) * 1024 + h * 64;
        __half* p1 = p0 + 8 * 1024;
        #pragma unroll
        for (int no = 0; no < 8; no++) {
            *(uint32_t*)(p0 + no * 8 + tig * 2) =
                h2pack(o[mt][no][0] * rs[mt][0], o[mt][no][1] * rs[mt][0]);
            *(uint32_t*)(p1 + no * 8 + tig * 2) =
                h2pack(o[mt][no][2] * rs[mt][1], o[mt][no][3] * rs[mt][1]);
        }
    }
}

// ============================================================
// Temporal attention (N=16), fp16 in/out, fp32 accumulate.
// ============================================================
__global__ void attn16_kernel(const __half* __restrict__ qkv, __half* __restrict__ out)
{
    constexpr int N = 16;
    const int tid = threadIdx.x;
    const int bh = blockIdx.x * 16 + (tid >> 4);
    const int h = bh & 15;
    const int batch = bh >> 4;
    const int row = tid & 15;
    const __half* base = qkv + (size_t)batch * N * 3072;

    __half2 q2[32];
    {
        const uint4* qp = reinterpret_cast<const uint4*>(base + (size_t)row * 3072 + h * 64);
        #pragma unroll
        for (int c = 0; c < 8; c++) *(uint4*)(q2 + c * 4) = qp[c];
    }

    float2 acc[32];
    #pragma unroll
    for (int d = 0; d < 32; d++) acc[d] = make_float2(0.f, 0.f);
    float sum = 0.f;
    #pragma unroll
    for (int j = 0; j < N; j++) {
        __half2 k2[32];
        const uint4* kp = reinterpret_cast<const uint4*>(base + (size_t)j * 3072 + 1024 + h * 64);
        #pragma unroll
        for (int c = 0; c < 8; c++) *(uint4*)(k2 + c * 4) = kp[c];
        float s = 0.f;
        #pragma unroll
        for (int d = 0; d < 32; d++) {
            const float2 qd = __half22float2(q2[d]);
            const float2 kd = __half22float2(k2[d]);
            s += qd.x * kd.x + qd.y * kd.y;
        }
        const float e = fexp_shift(s);
        sum += e;
        __half2 v2[32];
        const uint4* vp = reinterpret_cast<const uint4*>(base + (size_t)j * 3072 + 2048 + h * 64);
        #pragma unroll
        for (int c = 0; c < 8; c++) *(uint4*)(v2 + c * 4) = vp[c];
        #pragma unroll
        for (int d = 0; d < 32; d++) {
            const float2 vd = __half22float2(v2[d]);
            acc[d].x += e * vd.x;
            acc[d].y += e * vd.y;
        }
    }
    const float inv = 1.f / sum;
    uint32_t* op = reinterpret_cast<uint32_t*>(out + ((size_t)batch * N + row) * 1024 + h * 64);
    #pragma unroll
    for (int d = 0; d < 32; d++)
        op[d] = h2pack(acc[d].x * inv, acc[d].y * inv);
}

// ============================================================
// fp16 tensor-core GEMM. QKVLN fuses per-head LN of q,k (+qscale)
// into the epilogue: warp N-tile (64 cols) == one head vector;
// stats via 2 shfl_xor over the 4 lanes sharing g.
// ============================================================
constexpr int STG_B    = 32768;
constexpr int GEMM_SMEM = 2 * STG_B;

template<bool GELU, bool HALFOUT, bool PERMROW, bool QKVLN>
__global__ __launch_bounds__(256, 2) void gemm_mma(
    const __half* __restrict__ A, const __half* __restrict__ Bt,
    void* __restrict__ Cv, const float* __restrict__ bias,
    const float* __restrict__ resid, int M, int N, int K,
    const float* __restrict__ hn_w, const float* __restrict__ hn_b, float qscale)
{
    extern __shared__ float sm[];
    const uint32_t stg = smem_u32(sm);

    const int tid = threadIdx.x;
    const int wid = tid >> 5, lane = tid & 31;
    const int g = lane >> 2, tig = lane & 3;
    const int warpM = wid & 3, warpN = wid >> 2;
    const int bx = blockIdx.x, by = blockIdx.y;
    const int NKB = K >> 6;

    uint32_t a_s[4], b_s[4];
    const __half *a_g[4], *b_g[4];
    #pragma unroll
    for (int t = 0; t < 4; t++) {
        const int idx = tid + (t << 8);
        const int r = idx >> 3, c = idx & 7;
        const uint32_t sw = (uint32_t)(r * 128 + ((c ^ (r & 7)) << 4));
        a_s[t] = sw;            b_s[t] = sw + 16384;
        a_g[t] = A  + (size_t)(by * 128 + r) * K + c * 8;
        b_g[t] = Bt + (size_t)(bx * 128 + r) * K + c * 8;
    }

    auto load_stage = [&](int s, int kb) {
        const uint32_t sb = stg + s * STG_B;
        const int ko = kb << 6;
        #pragma unroll
        for (int t = 0; t < 4; t++)
            asm volatile("cp.async.cg.shared.global [%0], [%1], 16;" ::
                "r"(sb + a_s[t]), "l"(a_g[t] + ko) : "memory");
        #pragma unroll
        for (int t = 0; t < 4; t++)
            asm volatile("cp.async.cg.shared.global [%0], [%1], 16;" ::
                "r"(sb + b_s[t]), "l"(b_g[t] + ko) : "memory");
    };

    const int lr = lane & 7;
    const int aRow = warpM * 32 + ((lane >> 3) & 1) * 8 + lr;
    const int cbA  = lane >> 4;
    const uint32_t aRx = (uint32_t)(aRow * 128);
    const uint32_t a7  = (uint32_t)(aRow & 7);
    const int bRow = warpN * 64 + (lane >> 4) * 8 + lr;
    const int cbB  = (lane >> 3) & 1;
    const uint32_t bRx = (uint32_t)(bRow * 128);
    const uint32_t b7  = (uint32_t)(bRow & 7);

    float acc[2][8][4];
    #pragma unroll
    for (int mt = 0; mt < 2; mt++)
        #pragma unroll
        for (int nt = 0; nt < 8; nt++)
            #pragma unroll
            for (int i = 0; i < 4; i++) acc[mt][nt][i] = 0.f;

    load_stage(0, 0);
    asm volatile("cp.async.commit_group;" ::: "memory");

    for (int kb = 0; kb < NKB; kb++) {
        if (kb + 1 < NKB) {
            load_stage((kb + 1) & 1, kb + 1);
            asm volatile("cp.async.commit_group;" ::: "memory");
            asm volatile("cp.async.wait_group 1;" ::: "memory");
        } else {
            asm volatile("cp.async.wait_group 0;" ::: "memory");
        }
        __syncthreads();

        const uint32_t sA = stg + (kb & 1) * STG_B;
        const uint32_t sB = sA + 16384;
        #pragma unroll
        for (int ks = 0; ks < 4; ks++) {
            uint32_t a[2][4], b[8][2];
            const uint32_t swA = ((uint32_t)(2 * ks + cbA) ^ a7) << 4;
            #pragma unroll
            for (int mt = 0; mt < 2; mt++)
                ldsm4(a[mt][0], a[mt][1], a[mt][2], a[mt][3],
                      sA + aRx + (uint32_t)(mt * 16 * 128) + swA);
            const uint32_t swB = ((uint32_t)(2 * ks + cbB) ^ b7) << 4;
            #pragma unroll
            for (int ntp = 0; ntp < 4; ntp++)
                ldsm4(b[2 * ntp][0], b[2 * ntp][1], b[2 * ntp + 1][0], b[2 * ntp + 1][1],
                      sB + bRx + (uint32_t)(ntp * 16 * 128) + swB);
            #pragma unroll
            for (int mt = 0; mt < 2; mt++)
                #pragma unroll
                for (int nt = 0; nt < 8; nt++)
                    mma_f16(acc[mt][nt], a[mt], b[nt]);
        }
        __syncthreads();
    }

    // ---- epilogue ----
    // QKVLN path: which = (bx*128 + warpN*64)/1024 -> 0 q (LN*qscale),
    // 1 k (LN), 2 v (passthrough). Head-local col = nt*8 + tig*2 + j.
    const int colblk = bx * 128 + warpN * 64;
    const int which = QKVLN ? (colblk >> 10) : 2;
    const float lnscale = (which == 0) ? qscale : 1.f;

    #pragma unroll
    for (int mt = 0; mt < 2; mt++) {
        #pragma unroll
        for (int half = 0; half < 2; half++) {
            int row = by * 128 + warpM * 32 + mt * 16 + g + half * 8;
            if (PERMROW) {
                const int t = row & 15, s = (row >> 4) & 255, bb = row >> 12;
                row = bb * 4096 + t * 256 + s;
            }
            float mean = 0.f, rstd = 1.f;
            if (QKVLN && which < 2) {
                float s1 = 0.f, s2 = 0.f;
                #pragma unroll
                for (int nt = 0; nt < 8; nt++) {
                    const float u0 = acc[mt][nt][half * 2 + 0];
                    const float u1 = acc[mt][nt][half * 2 + 1];
                    s1 += u0 + u1;
                    s2 += u0 * u0 + u1 * u1;
                }
                s1 += __shfl_xor_sync(0xffffffffu, s1, 1);
                s2 += __shfl_xor_sync(0xffffffffu, s2, 1);
                s1 += __shfl_xor_sync(0xffffffffu, s1, 2);
                s2 += __shfl_xor_sync(0xffffffffu, s2, 2);
                mean = s1 * (1.f / 64.f);
                rstd = rsqrtf(s2 * (1.f / 64.f) - mean * mean + EPSF);
            }
            const float* rp = resid ? resid + (size_t)row * N : nullptr;
            #pragma unroll
            for (int nt = 0; nt < 8; nt++) {
                const int col = colblk + nt * 8 + tig * 2;
                float v0 = acc[mt][nt][half * 2 + 0];
                float v1 = acc[mt][nt][half * 2 + 1];
                if (QKVLN) {
                    if (which < 2) {
                        const int hc = nt * 8 + tig * 2;
                        v0 = ((v0 - mean) * rstd * hn_w[hc]     + hn_b[hc])     * lnscale;
                        v1 = ((v1 - mean) * rstd * hn_w[hc + 1] + hn_b[hc + 1]) * lnscale;
                    }
                } else {
                    if (bias) { v0 += bias[col]; v1 += bias[col + 1]; }
                    if (rp)   { v0 += rp[col];   v1 += rp[col + 1]; }
                    if (GELU) {
                        v0 = 0.5f * v0 * (1.f + erff(v0 * 0.70710678f));
                        v1 = 0.5f * v1 * (1.f + erff(v1 * 0.70710678f));
                    }
                }
                if (HALFOUT) {
                    __half* cp = (__half*)Cv + (size_t)row * N + col;
                    *(uint32_t*)cp = h2pack(v0, v1);
                } else {
                    float* cp = (float*)Cv + (size_t)row * N + col;
                    float2 v; v.x = v0; v.y = v1;
                    *(float2*)cp = v;
                }
            }
        }
    }
}

// ============================================================
extern "C" void kernel_launch(void* const* d_in, const int* /*in_sizes*/, int /*n_in*/,
                              void* d_out, int /*out_size*/)
{
    const float* x        = (const float*)d_in[0];
    const float* ns_w     = (const float*)d_in[1];
    const float* ns_b     = (const float*)d_in[2];
    const float* nt_w     = (const float*)d_in[3];
    const float* nt_b     = (const float*)d_in[4];
    const float* nm_w     = (const float*)d_in[5];
    const float* nm_b     = (const float*)d_in[6];
    const float* s_qkv    = (const float*)d_in[7];
    const float* s_qkn_w  = (const float*)d_in[8];
    const float* s_qkn_b  = (const float*)d_in[9];
    const float* s_proj_w = (const float*)d_in[10];
    const float* s_proj_b = (const float*)d_in[11];
    const float* t_qkv    = (const float*)d_in[12];
    const float* t_qkn_w  = (const float*)d_in[13];
    const float* t_qkn_b  = (const float*)d_in[14];
    const float* t_proj_w = (const float*)d_in[15];
    const float* t_proj_b = (const float*)d_in[16];
    const float* fc1_w    = (const float*)d_in[17];
    const float* fc1_b    = (const float*)d_in[18];
    const float* fc2_w    = (const float*)d_in[19];
    const float* fc2_b    = (const float*)d_in[20];
    float* out = (float*)d_out;

    float *xbuf;
    __half *xln, *qkv, *attn, *hbuf;
    __half *wt_sqkv, *wt_sproj, *wt_tqkv, *wt_tproj, *wt_fc1, *wt_fc2;
    cudaGetSymbolAddress((void**)&xbuf, g_xbuf);
    cudaGetSymbolAddress((void**)&xln,  g_xln);
    cudaGetSymbolAddress((void**)&qkv,  g_qkv);
    cudaGetSymbolAddress((void**)&attn, g_attn);
    cudaGetSymbolAddress((void**)&hbuf, g_h);
    cudaGetSymbolAddress((void**)&wt_sqkv,  g_wt_sqkv);
    cudaGetSymbolAddress((void**)&wt_sproj, g_wt_sproj);
    cudaGetSymbolAddress((void**)&wt_tqkv,  g_wt_tqkv);
    cudaGetSymbolAddress((void**)&wt_tproj, g_wt_tproj);
    cudaGetSymbolAddress((void**)&wt_fc1,   g_wt_fc1);
    cudaGetSymbolAddress((void**)&wt_fc2,   g_wt_fc2);

    cudaFuncSetAttribute(attn_tc, cudaFuncAttributeMaxDynamicSharedMemorySize, ATTN_SMEM);
    cudaFuncSetAttribute((const void*)gemm_mma<false, false, false, false>,
                         cudaFuncAttributeMaxDynamicSharedMemorySize, GEMM_SMEM);
    cudaFuncSetAttribute((const void*)gemm_mma<false, true,  false, true>,
                         cudaFuncAttributeMaxDynamicSharedMemorySize, GEMM_SMEM);
    cudaFuncSetAttribute((const void*)gemm_mma<false, false, true,  false>,
                         cudaFuncAttributeMaxDynamicSharedMemorySize, GEMM_SMEM);
    cudaFuncSetAttribute((const void*)gemm_mma<true,  true,  false, false>,
                         cudaFuncAttributeMaxDynamicSharedMemorySize, GEMM_SMEM);

    // ---- weight transposes (+ fp16 rounding), once per launch ----
    dim3 tb(32, 8);
    transpose_w<<<dim3(3072/32, 1024/32), tb>>>(s_qkv,    wt_sqkv,  1024, 3072);
    transpose_w<<<dim3(1024/32, 1024/32), tb>>>(s_proj_w, wt_sproj, 1024, 1024);
    transpose_w<<<dim3(3072/32, 1024/32), tb>>>(t_qkv,    wt_tqkv,  1024, 3072);
    transpose_w<<<dim3(1024/32, 1024/32), tb>>>(t_proj_w, wt_tproj, 1024, 1024);
    transpose_w<<<dim3(4096/32, 1024/32), tb>>>(fc1_w,    wt_fc1,   1024, 4096);
    transpose_w<<<dim3(1024/32, 4096/32), tb>>>(fc2_w,    wt_fc2,   4096, 1024);

    // ---- spatial attention block ----
    ln_kernel<false><<<R_, 256>>>(x, xln, ns_w, ns_b);
    gemm_mma<false, true, false, true><<<dim3(24, 64), 256, GEMM_SMEM>>>(
        xln, wt_sqkv, qkv, nullptr, nullptr, R_, 3072, 1024, s_qkn_w, s_qkn_b, SCALE_);
    attn_tc<<<B_ * T_ * H_, 256, ATTN_SMEM>>>(qkv, attn);
    gemm_mma<false, false, false, false><<<dim3(8, 64), 256, GEMM_SMEM>>>(
        attn, wt_sproj, xbuf, s_proj_b, x, R_, 1024, 1024, nullptr, nullptr, 1.f);

    // ---- temporal attention block (permutes fused into ln + gemm) ----
    ln_kernel<true><<<R_, 256>>>(xbuf, xln, nt_w, nt_b);
    gemm_mma<false, true, false, true><<<dim3(24, 64), 256, GEMM_SMEM>>>(
        xln, wt_tqkv, qkv, nullptr, nullptr, R_, 3072, 1024, t_qkn_w, t_qkn_b, SCALE_);
    attn16_kernel<<<(B_ * S_ * H_) / 16, 256>>>(qkv, attn);
    gemm_mma<false, false, true, false><<<dim3(8, 64), 256, GEMM_SMEM>>>(
        attn, wt_tproj, xbuf, t_proj_b, xbuf, R_, 1024, 1024, nullptr, nullptr, 1.f);

    // ---- MLP ----
    ln_kernel<false><<<R_, 256>>>(xbuf, xln, nm_w, nm_b);
    gemm_mma<true,  true,  false, false><<<dim3(32, 64), 256, GEMM_SMEM>>>(
        xln, wt_fc1, hbuf, fc1_b, nullptr, R_, 4096, 1024, nullptr, nullptr, 1.f);
    gemm_mma<false, false, false, false><<<dim3(8, 64), 256, GEMM_SMEM>>>(
        hbuf, wt_fc2, out, fc2_b, xbuf, R_, 1024, 4096, nullptr, nullptr, 1.f);
}